// round 10
// baseline (speedup 1.0000x reference)
#include <cuda_runtime.h>
#include <cuda_fp16.h>
#include <cstdint>

typedef unsigned int u32;
typedef unsigned long long u64;

#define NB 4
#define NC 256
#define NHW 4096

// ---------------- device scratch ----------------
__device__ __align__(16) __half g_CM_hi[27][64][256];   // combined matrices (fp16)
__device__ float g_pp_sum[27][4][8][64];
__device__ float g_pp_max[27][4][8][64];
// x transposed, fp16 hi plane: [src*4+b][hw 4096][cin 256]
__device__ __align__(16) __half g_xT_hi[12u * 4096u * 256u];
// gated output weights (fp16 hi): [b][ct2][s][128][256]
__device__ __align__(16) __half g_W5[4 * 2 * 3 * 128 * 256];

// ---------------- helpers ----------------
static __device__ __forceinline__ u32 smem_u32(const void* p) {
    return (u32)__cvta_generic_to_shared(p);
}
static __device__ __forceinline__ void cp16(u32 d, const void* s) {
    asm volatile("cp.async.cg.shared.global [%0], [%1], 16;" :: "r"(d), "l"(s));
}
#define CP_COMMIT() asm volatile("cp.async.commit_group;" ::: "memory")
#define CP_WAIT1()  asm volatile("cp.async.wait_group 1;" ::: "memory")
#define CP_WAIT0()  asm volatile("cp.async.wait_group 0;" ::: "memory")

static __device__ __forceinline__ void ldsm4(u32* r, u32 a) {
    asm volatile("ldmatrix.sync.aligned.m8n8.x4.shared.b16 {%0,%1,%2,%3}, [%4];"
                 : "=r"(r[0]), "=r"(r[1]), "=r"(r[2]), "=r"(r[3]) : "r"(a));
}
static __device__ __forceinline__ void mma16816(float* d, const u32* a, const u32* b) {
    asm volatile(
        "mma.sync.aligned.m16n8k16.row.col.f32.f16.f16.f32 "
        "{%0,%1,%2,%3},{%4,%5,%6,%7},{%8,%9},{%0,%1,%2,%3};"
        : "+f"(d[0]), "+f"(d[1]), "+f"(d[2]), "+f"(d[3])
        : "r"(a[0]), "r"(a[1]), "r"(a[2]), "r"(a[3]), "r"(b[0]), "r"(b[1]));
}

// smem layout (bytes). Rows: 256 fp16 = 512B + 16B pad = 528B
#define ROWB     528
#define BBUF     33792            // 64 rows * 528 (one plane)
// k2: A [192 rows] + 2 B buffers
#define K2_SMB   101376           // 192*528
#define K2_SMEM  (K2_SMB + 2 * BBUF)     // 168960
// k5: A [64 rows] + 2 B buffers
#define K5_SMB   33792
#define K5_SMEM  (K5_SMB + 2 * BBUF)     // 101376

// ============================================================================
// K0: transpose + fp16 x -> g_xT_hi [src*4+b][hw][cin]
// ============================================================================
__global__ void k0_split(const float* __restrict__ xt, const float* __restrict__ xb,
                         const float* __restrict__ xm) {
    int sb = blockIdx.x;
    int src = sb >> 2, b = sb & 3;
    const float* xs = (src == 0) ? xt : (src == 1) ? xb : xm;
    int cin0 = blockIdx.y * 32, hw0 = blockIdx.z * 256;
    __shared__ float s[32][257];
    const float* base = xs + ((size_t)b * NC + cin0) * NHW + hw0;
    for (int i = threadIdx.x; i < 32 * 256; i += 256) {
        int r = i >> 8, c = i & 255;
        s[r][c] = base[(size_t)r * NHW + c];
    }
    __syncthreads();
    int t = threadIdx.x;
    u32 hb[16];
#pragma unroll
    for (int m = 0; m < 16; m++) {
        __half h0 = __float2half_rn(s[2 * m][t]);
        __half h1 = __float2half_rn(s[2 * m + 1][t]);
        hb[m] = (u32)__half_as_ushort(h0) | ((u32)__half_as_ushort(h1) << 16);
    }
    size_t ro = ((size_t)sb * 4096 + hw0 + t) * 256 + cin0;
    uint4* dh = (uint4*)&g_xT_hi[ro];
#pragma unroll
    for (int q = 0; q < 4; q++)
        dh[q] = make_uint4(hb[4 * q], hb[4 * q + 1], hb[4 * q + 2], hb[4 * q + 3]);
}

// ============================================================================
// K1: combined matrices Wred[e]@Wqkv[w] -> fp16 g_CM_hi[combo][cp][cin]
// ============================================================================
__global__ void k1_cm(const float* __restrict__ Wqkv, const float* __restrict__ Wred) {
    int combo = blockIdx.x;
    int e = combo / 3, r = combo % 3;
    int ii = e / 3, jj = e % 3;
    int w = (r == 0) ? 3 * jj : (r == 1) ? (3 * ii + 1) : (3 * jj + 2);
    int cc0 = blockIdx.y * 64;

    __shared__ float sA[64][65];
    __shared__ float sB[64][65];

    int tx = threadIdx.x & 15, ty = threadIdx.x >> 4;
    float acc[4][4] = {};

    const float* A = Wred + (size_t)e * 64 * 256;
    const float* Bm = Wqkv + (size_t)w * 65536;

    for (int k0 = 0; k0 < 256; k0 += 64) {
        for (int idx = threadIdx.x; idx < 4096; idx += 256) {
            int rr = idx >> 6, cl = idx & 63;
            sA[rr][cl] = A[rr * 256 + k0 + cl];
            sB[rr][cl] = Bm[(k0 + rr) * 256 + cc0 + cl];
        }
        __syncthreads();
#pragma unroll
        for (int kk = 0; kk < 64; kk++) {
            float av[4], bv[4];
#pragma unroll
            for (int u = 0; u < 4; u++) av[u] = sA[ty * 4 + u][kk];
#pragma unroll
            for (int v = 0; v < 4; v++) bv[v] = sB[kk][tx * 4 + v];
#pragma unroll
            for (int u = 0; u < 4; u++)
#pragma unroll
                for (int v = 0; v < 4; v++) acc[u][v] = fmaf(av[u], bv[v], acc[u][v]);
        }
        __syncthreads();
    }
#pragma unroll
    for (int u = 0; u < 4; u++)
#pragma unroll
        for (int v = 0; v < 4; v++)
            g_CM_hi[combo][ty * 4 + u][cc0 + tx * 4 + v] = __float2half_rn(acc[u][v]);
}

// ---- plane loader: 64 hw rows (2048 x 16B chunks) ----
static __device__ __forceinline__ void load_plane(
    u32 dst, const __half* X, int hw0, int tid, int nthr) {
    for (int f = tid; f < 2048; f += nthr) {
        int row = f >> 5, c = f & 31;
        cp16(dst + row * ROWB + c * 16, X + (size_t)(hw0 + row) * 256 + c * 8);
    }
}

// ============================================================================
// K2: HMMA reduced projection (fp16 1-term) + relu + pool.
//     grid (9 = 3src*3mt, 4 b, 8 z of 512 hw), block 384 (6m x 2n warps).
//     M tile = 192 rows (3 combos); 8 steps of 64 hw, double-buffered B.
// ============================================================================
__global__ void __launch_bounds__(384, 1)
k2_mma() {
    extern __shared__ __align__(16) char sm[];
    u32 smb = smem_u32(sm);

    int tid = threadIdx.x, wid = tid >> 5, lane = tid & 31;
    int src = blockIdx.x / 3, mt = blockIdx.x % 3;
    int b = blockIdx.y, z = blockIdx.z;

    int list[9];
    int n = 0;
    for (int combo = 0; combo < 27; combo++) {
        int e = combo / 3, r = combo % 3;
        int sc = (r == 1) ? e / 3 : e % 3;
        if (sc == src) list[n++] = combo;
    }

    const __half* XH = g_xT_hi + (size_t)(src * 4 + b) * 4096 * 256;

    // A load: 192 rows x 32 chunks = 6144 chunks / 384 thr = 16 iters
#pragma unroll
    for (int i = 0; i < 16; i++) {
        int f = tid + i * 384;
        int row = f >> 5, c = f & 31;
        int cb = list[3 * mt + (row >> 6)];
        size_t so = ((size_t)cb * 64 + (row & 63)) * 256 + c * 8;
        cp16(smb + row * ROWB + c * 16, &g_CM_hi[0][0][0] + so);
    }
    CP_COMMIT();
    load_plane(smb + K2_SMB, XH, z * 512, tid, 384);
    CP_COMMIT();

    int mwarp = wid >> 1, nwarp = wid & 1;   // 6 x 2
    int R0 = mwarp * 32;
    int H = nwarp * 32;

    u32 aoff = (u32)(R0 + (lane & 15)) * ROWB + (lane >> 4) * 16;
    u32 aHi = smb + aoff;
    u32 boff = (u32)(H + (lane & 7) + ((lane >= 16) ? 8 : 0)) * ROWB + ((lane & 8) ? 16 : 0);

    float psum[2][2] = {}, pmax[2][2] = {};

    for (int step = 0; step < 8; step++) {
        if (step < 7) {
            load_plane(smb + K2_SMB + ((step + 1) & 1) * BBUF, XH, z * 512 + (step + 1) * 64,
                       tid, 384);
            CP_COMMIT();
            CP_WAIT1();
        } else {
            CP_WAIT0();
        }
        __syncthreads();

        u32 bHi = smb + K2_SMB + (step & 1) * BBUF + boff;

        float acc[2][4][4] = {};
#pragma unroll
        for (int kk = 0; kk < 16; kk++) {
            u32 kb = kk * 32;
            u32 ah0[4], ah1[4], bh0[4], bh1[4];
            ldsm4(ah0, aHi + kb);
            ldsm4(ah1, aHi + 16 * ROWB + kb);
            ldsm4(bh0, bHi + kb);
            ldsm4(bh1, bHi + 16 * ROWB + kb);
#pragma unroll
            for (int m = 0; m < 2; m++) {
                const u32* ah = m ? ah1 : ah0;
                mma16816(acc[m][0], ah, bh0);
                mma16816(acc[m][1], ah, bh0 + 2);
                mma16816(acc[m][2], ah, bh1);
                mma16816(acc[m][3], ah, bh1 + 2);
            }
        }
#pragma unroll
        for (int m = 0; m < 2; m++)
#pragma unroll
            for (int nt = 0; nt < 4; nt++) {
                float r0 = fmaxf(acc[m][nt][0], 0.f), r1 = fmaxf(acc[m][nt][1], 0.f);
                float r2 = fmaxf(acc[m][nt][2], 0.f), r3 = fmaxf(acc[m][nt][3], 0.f);
                psum[m][0] += r0 + r1;
                psum[m][1] += r2 + r3;
                pmax[m][0] = fmaxf(pmax[m][0], fmaxf(r0, r1));
                pmax[m][1] = fmaxf(pmax[m][1], fmaxf(r2, r3));
            }
        __syncthreads();
    }

#pragma unroll
    for (int m = 0; m < 2; m++)
#pragma unroll
        for (int h = 0; h < 2; h++) {
#pragma unroll
            for (int off = 1; off <= 2; off <<= 1) {
                psum[m][h] += __shfl_xor_sync(0xffffffffu, psum[m][h], off);
                pmax[m][h] = fmaxf(pmax[m][h], __shfl_xor_sync(0xffffffffu, pmax[m][h], off));
            }
        }

    float* ps = (float*)(sm + K2_SMB);       // [192][2]
    float* pm = ps + 384;
    if ((lane & 3) == 0) {
        int g = lane >> 2;
#pragma unroll
        for (int m = 0; m < 2; m++)
#pragma unroll
            for (int h = 0; h < 2; h++) {
                int row = R0 + m * 16 + h * 8 + g;
                ps[row * 2 + nwarp] = psum[m][h];
                pm[row * 2 + nwarp] = pmax[m][h];
            }
    }
    __syncthreads();
    if (tid < 192) {
        float s = ps[tid * 2] + ps[tid * 2 + 1];
        float m = fmaxf(pm[tid * 2], pm[tid * 2 + 1]);
        int cb = list[3 * mt + (tid >> 6)];
        g_pp_sum[cb][b][z][tid & 63] = s;
        g_pp_max[cb][b][z][tid & 63] = m;
    }
}

// ============================================================================
// K34: fused channel-attention gates + gated W5 build (fp16 hi).
//      grid (4 b, 2 ct2, 3 s), block 256. Gates recomputed per block (tiny).
// ============================================================================
__global__ void k34(const float* __restrict__ Wrec, const float* __restrict__ Wqkv) {
    int b = blockIdx.x, ct = blockIdx.y, s = blockIdx.z;
    __shared__ float fS[64], gS[64], hS[64];
    __shared__ float redA[4][64], redB[4][64];
    __shared__ float vall[9][64];
    __shared__ float og[9][128];
    __shared__ float sAc[128], sBc[128];
    int tid = threadIdx.x;
    int j = tid & 63, p = tid >> 6;

    for (int e = 0; e < 9; e++) {
        __syncthreads();
        if (p < 3) {
            float sv = 0.f, m = 0.f;
#pragma unroll
            for (int ch = 0; ch < 8; ch++) {
                sv += g_pp_sum[e * 3 + p][b][ch][j];
                m = fmaxf(m, g_pp_max[e * 3 + p][b][ch][j]);
            }
            float val = sv * (1.f / 4096.f) + m;
            if (p == 0) gS[j] = val;        // pool(qr)
            else if (p == 1) fS[j] = val;   // pool(kr)
            else hS[j] = val;               // pool(vr)
        }
        __syncthreads();

        float gj = gS[j];
        float lmax = -1e30f;
#pragma unroll
        for (int i = p * 16; i < p * 16 + 16; i++) lmax = fmaxf(lmax, fS[i] * gj);
        redA[p][j] = lmax;
        __syncthreads();
        float mx = fmaxf(fmaxf(redA[0][j], redA[1][j]), fmaxf(redA[2][j], redA[3][j]));
        __syncthreads();
        float den = 0.f, num = 0.f;
#pragma unroll
        for (int i = p * 16; i < p * 16 + 16; i++) {
            float ev = expf(fS[i] * gj - mx);
            den += ev;
            num += hS[i] * ev;
        }
        redA[p][j] = den;
        redB[p][j] = num;
        __syncthreads();
        if (p == 0)
            vall[e][j] = (redB[0][j] + redB[1][j] + redB[2][j] + redB[3][j]) /
                         (redA[0][j] + redA[1][j] + redA[2][j] + redA[3][j]);
    }
    __syncthreads();

    // gates for this ct's 128 channels, all 9 e
    for (int idx = tid; idx < 9 * 128; idx += 256) {
        int e = idx >> 7, c = idx & 127;
        int cg = ct * 128 + c;
        const float* wr = Wrec + ((size_t)e * 256 + cg) * 64;
        float acc = 0.f;
#pragma unroll 8
        for (int q = 0; q < 64; q++) acc = fmaf(vall[e][q], wr[q], acc);
        og[e][c] = 1.f / (1.f + expf(-acc));
    }
    __syncthreads();

    if (tid < 128) {
        sAc[tid] = og[s][tid] + og[s + 3][tid] + og[s + 6][tid];
        sBc[tid] = og[3 * s][tid] + og[3 * s + 1][tid] + og[3 * s + 2][tid];
    }
    __syncthreads();

    const float* Wq = Wqkv + (size_t)(3 * s) * 65536 + (size_t)ct * 128 * 256;
    const float* Wk = Wq + 65536;
    const float* Wv = Wk + 65536;
    size_t base = ((size_t)(b * 2 + ct) * 3 + s) * 128 * 256;
    for (int i = tid; i < 128 * 256; i += 256) {
        int row = i >> 8, cin = i & 255;
        float w = sAc[row] * (Wq[row * 256 + cin] + Wv[row * 256 + cin])
                + sBc[row] * Wk[row * 256 + cin];
        g_W5[base + i] = __float2half_rn(w);
    }
}

// ============================================================================
// K5: HMMA output GEMM (fp16 1-term), accumulate 3 sources.
//     grid (4 ct of 64 ch, 4 b, 16 hz of 256 hw), block 128 (2m x 2n warps).
//     4 steps of 64 hw per s, double-buffered B. 2 CTAs/SM.
// ============================================================================
__global__ void __launch_bounds__(128, 2)
k5_mma(float* __restrict__ out) {
    extern __shared__ __align__(16) char sm[];
    u32 smb = smem_u32(sm);

    int tid = threadIdx.x, wid = tid >> 5, lane = tid & 31;
    int ct = blockIdx.x, b = blockIdx.y, hz = blockIdx.z;
    int ct2 = ct >> 1, half = ct & 1;

    int mwarp = wid >> 1, nwarp = wid & 1;
    int R0 = mwarp * 32;
    int H = nwarp * 32;

    u32 aoff = (u32)(R0 + (lane & 15)) * ROWB + (lane >> 4) * 16;
    u32 aHi = smb + aoff;
    u32 boff = (u32)(H + (lane & 7) + ((lane >= 16) ? 8 : 0)) * ROWB + ((lane & 8) ? 16 : 0);

    float acc[4][2][4][4] = {};   // [step][m][nt][4]

    // prologue: A(0), B(0, step0)
    {
        const __half* WA = g_W5 + ((size_t)(b * 2 + ct2) * 3) * 128 * 256
                         + (size_t)half * 64 * 256;
#pragma unroll
        for (int i = 0; i < 16; i++) {
            int f = tid + i * 128;
            int row = f >> 5, c = f & 31;
            cp16(smb + row * ROWB + c * 16, WA + (size_t)row * 256 + c * 8);
        }
        CP_COMMIT();
        load_plane(smb + K5_SMB, g_xT_hi + (size_t)b * 4096 * 256, hz * 256, tid, 128);
        CP_COMMIT();
    }

    for (int s = 0; s < 3; s++) {
        const __half* XH = g_xT_hi + (size_t)(s * 4 + b) * 4096 * 256;

#pragma unroll
        for (int step = 0; step < 4; step++) {
            CP_WAIT0();
            __syncthreads();

            if (step < 3) {
                load_plane(smb + K5_SMB + ((step + 1) & 1) * BBUF, XH,
                           hz * 256 + (step + 1) * 64, tid, 128);
                CP_COMMIT();
            }

            u32 bHi = smb + K5_SMB + (step & 1) * BBUF + boff;
#pragma unroll
            for (int kk = 0; kk < 16; kk++) {
                u32 kb = kk * 32;
                u32 ah0[4], ah1[4], bh0[4], bh1[4];
                ldsm4(ah0, aHi + kb);
                ldsm4(ah1, aHi + 16 * ROWB + kb);
                ldsm4(bh0, bHi + kb);
                ldsm4(bh1, bHi + 16 * ROWB + kb);
#pragma unroll
                for (int m = 0; m < 2; m++) {
                    const u32* ah = m ? ah1 : ah0;
                    mma16816(acc[step][m][0], ah, bh0);
                    mma16816(acc[step][m][1], ah, bh0 + 2);
                    mma16816(acc[step][m][2], ah, bh1);
                    mma16816(acc[step][m][3], ah, bh1 + 2);
                }
            }
            __syncthreads();

            if (step == 3 && s < 2) {
                const __half* WA = g_W5 + ((size_t)(b * 2 + ct2) * 3 + (s + 1)) * 128 * 256
                                 + (size_t)half * 64 * 256;
#pragma unroll
                for (int i = 0; i < 16; i++) {
                    int f = tid + i * 128;
                    int row = f >> 5, c = f & 31;
                    cp16(smb + row * ROWB + c * 16, WA + (size_t)row * 256 + c * 8);
                }
                CP_COMMIT();
                load_plane(smb + K5_SMB, g_xT_hi + (size_t)((s + 1) * 4 + b) * 4096 * 256,
                           hz * 256, tid, 128);
                CP_COMMIT();
            }
        }
    }

    // store
    int g = lane >> 2, t = lane & 3;
#pragma unroll
    for (int step = 0; step < 4; step++)
#pragma unroll
        for (int m = 0; m < 2; m++)
#pragma unroll
            for (int nt = 0; nt < 4; nt++) {
                int ch = ct * 64 + R0 + m * 16 + g;
                int col = hz * 256 + step * 64 + H + nt * 8 + 2 * t;
                float2* p0 = (float2*)(out + ((size_t)b * NC + ch) * NHW + col);
                float2* p1 = (float2*)(out + ((size_t)b * NC + ch + 8) * NHW + col);
                *p0 = make_float2(acc[step][m][nt][0], acc[step][m][nt][1]);
                *p1 = make_float2(acc[step][m][nt][2], acc[step][m][nt][3]);
            }
}

// ============================================================================
extern "C" void kernel_launch(void* const* d_in, const int* in_sizes, int n_in,
                              void* d_out, int out_size) {
    (void)in_sizes; (void)n_in; (void)out_size;
    const float* t    = (const float*)d_in[0];
    const float* bb   = (const float*)d_in[1];
    const float* mm   = (const float*)d_in[2];
    const float* Wqkv = (const float*)d_in[3];
    const float* Wred = (const float*)d_in[4];
    const float* Wrec = (const float*)d_in[5];
    float* out = (float*)d_out;

    cudaFuncSetAttribute(k2_mma, cudaFuncAttributeMaxDynamicSharedMemorySize, K2_SMEM);
    cudaFuncSetAttribute(k5_mma, cudaFuncAttributeMaxDynamicSharedMemorySize, K5_SMEM);

    k0_split<<<dim3(12, 8, 16), 256>>>(t, bb, mm);
    k1_cm<<<dim3(27, 4), 256>>>(Wqkv, Wred);
    k2_mma<<<dim3(9, 4, 8), 384, K2_SMEM>>>();
    k34<<<dim3(4, 2, 3), 256>>>(Wrec, Wqkv);
    k5_mma<<<dim3(4, 4, 16), 128, K5_SMEM>>>(out);
}

// round 11
// speedup vs baseline: 1.2501x; 1.2501x over previous
#include <cuda_runtime.h>
#include <cuda_fp16.h>
#include <cstdint>

typedef unsigned int u32;
typedef unsigned long long u64;

#define NB 4
#define NC 256
#define NHW 4096

// ---------------- device scratch ----------------
__device__ __align__(16) __half g_CM_hi[27][64][256];   // combined matrices (fp16)
__device__ float g_pp_sum[27][4][8][64];
__device__ float g_pp_max[27][4][8][64];
__device__ float g_o[9][4][256];
// x transposed, fp16 hi plane: [src*4+b][hw 4096][cin 256]
__device__ __align__(16) __half g_xT_hi[12u * 4096u * 256u];
// gated output weights (fp16): [b][ct2][s][128][256]
__device__ __align__(16) __half g_W5[4 * 2 * 3 * 128 * 256];

// ---------------- helpers ----------------
static __device__ __forceinline__ u32 smem_u32(const void* p) {
    return (u32)__cvta_generic_to_shared(p);
}
static __device__ __forceinline__ void cp16(u32 d, const void* s) {
    asm volatile("cp.async.cg.shared.global [%0], [%1], 16;" :: "r"(d), "l"(s));
}
#define CP_COMMIT() asm volatile("cp.async.commit_group;" ::: "memory")
#define CP_WAIT1()  asm volatile("cp.async.wait_group 1;" ::: "memory")
#define CP_WAIT0()  asm volatile("cp.async.wait_group 0;" ::: "memory")

static __device__ __forceinline__ void ldsm4(u32* r, u32 a) {
    asm volatile("ldmatrix.sync.aligned.m8n8.x4.shared.b16 {%0,%1,%2,%3}, [%4];"
                 : "=r"(r[0]), "=r"(r[1]), "=r"(r[2]), "=r"(r[3]) : "r"(a));
}
static __device__ __forceinline__ void mma16816(float* d, const u32* a, const u32* b) {
    asm volatile(
        "mma.sync.aligned.m16n8k16.row.col.f32.f16.f16.f32 "
        "{%0,%1,%2,%3},{%4,%5,%6,%7},{%8,%9},{%0,%1,%2,%3};"
        : "+f"(d[0]), "+f"(d[1]), "+f"(d[2]), "+f"(d[3])
        : "r"(a[0]), "r"(a[1]), "r"(a[2]), "r"(a[3]), "r"(b[0]), "r"(b[1]));
}

// smem layout (bytes). Rows: 256 fp16 = 512B + 16B pad = 528B
#define ROWB     528
#define BBUF     33792            // 64 rows * 528 (one plane)
// k2: A [192 rows] + 2 B buffers
#define K2_SMB   101376           // 192*528
#define K2_SMEM  (K2_SMB + 2 * BBUF)     // 168960
// k5: A [64 rows] + 2 B buffers
#define K5_SMB   33792
#define K5_SMEM  (K5_SMB + 2 * BBUF)     // 101376

// ============================================================================
// K0: transpose + fp16 x -> g_xT_hi [src*4+b][hw][cin]
// ============================================================================
__global__ void k0_split(const float* __restrict__ xt, const float* __restrict__ xb,
                         const float* __restrict__ xm) {
    int sb = blockIdx.x;
    int src = sb >> 2, b = sb & 3;
    const float* xs = (src == 0) ? xt : (src == 1) ? xb : xm;
    int cin0 = blockIdx.y * 32, hw0 = blockIdx.z * 256;
    __shared__ float s[32][257];
    const float* base = xs + ((size_t)b * NC + cin0) * NHW + hw0;
    for (int i = threadIdx.x; i < 32 * 256; i += 256) {
        int r = i >> 8, c = i & 255;
        s[r][c] = base[(size_t)r * NHW + c];
    }
    __syncthreads();
    int t = threadIdx.x;
    u32 hb[16];
#pragma unroll
    for (int m = 0; m < 16; m++) {
        __half h0 = __float2half_rn(s[2 * m][t]);
        __half h1 = __float2half_rn(s[2 * m + 1][t]);
        hb[m] = (u32)__half_as_ushort(h0) | ((u32)__half_as_ushort(h1) << 16);
    }
    size_t ro = ((size_t)sb * 4096 + hw0 + t) * 256 + cin0;
    uint4* dh = (uint4*)&g_xT_hi[ro];
#pragma unroll
    for (int q = 0; q < 4; q++)
        dh[q] = make_uint4(hb[4 * q], hb[4 * q + 1], hb[4 * q + 2], hb[4 * q + 3]);
}

// ============================================================================
// K1: combined matrices Wred[e]@Wqkv[w] -> fp16 g_CM_hi[combo][cp][cin]
// ============================================================================
__global__ void k1_cm(const float* __restrict__ Wqkv, const float* __restrict__ Wred) {
    int combo = blockIdx.x;
    int e = combo / 3, r = combo % 3;
    int ii = e / 3, jj = e % 3;
    int w = (r == 0) ? 3 * jj : (r == 1) ? (3 * ii + 1) : (3 * jj + 2);
    int cc0 = blockIdx.y * 64;

    __shared__ float sA[64][65];
    __shared__ float sB[64][65];

    int tx = threadIdx.x & 15, ty = threadIdx.x >> 4;
    float acc[4][4] = {};

    const float* A = Wred + (size_t)e * 64 * 256;
    const float* Bm = Wqkv + (size_t)w * 65536;

    for (int k0 = 0; k0 < 256; k0 += 64) {
        for (int idx = threadIdx.x; idx < 4096; idx += 256) {
            int rr = idx >> 6, cl = idx & 63;
            sA[rr][cl] = A[rr * 256 + k0 + cl];
            sB[rr][cl] = Bm[(k0 + rr) * 256 + cc0 + cl];
        }
        __syncthreads();
#pragma unroll
        for (int kk = 0; kk < 64; kk++) {
            float av[4], bv[4];
#pragma unroll
            for (int u = 0; u < 4; u++) av[u] = sA[ty * 4 + u][kk];
#pragma unroll
            for (int v = 0; v < 4; v++) bv[v] = sB[kk][tx * 4 + v];
#pragma unroll
            for (int u = 0; u < 4; u++)
#pragma unroll
                for (int v = 0; v < 4; v++) acc[u][v] = fmaf(av[u], bv[v], acc[u][v]);
        }
        __syncthreads();
    }
#pragma unroll
    for (int u = 0; u < 4; u++)
#pragma unroll
        for (int v = 0; v < 4; v++)
            g_CM_hi[combo][ty * 4 + u][cc0 + tx * 4 + v] = __float2half_rn(acc[u][v]);
}

// ---- plane loader: 64 hw rows (2048 x 16B chunks) ----
static __device__ __forceinline__ void load_plane(
    u32 dst, const __half* X, int hw0, int tid, int nthr) {
    for (int f = tid; f < 2048; f += nthr) {
        int row = f >> 5, c = f & 31;
        cp16(dst + row * ROWB + c * 16, X + (size_t)(hw0 + row) * 256 + c * 8);
    }
}

// ============================================================================
// K2: HMMA reduced projection (fp16 1-term) + relu + pool.
//     grid (9 = 3src*3mt, 4 b, 8 z of 512 hw), block 384 (6m x 2n warps).
//     M tile = 192 rows (3 combos); 8 steps of 64 hw, double-buffered B.
// ============================================================================
__global__ void __launch_bounds__(384, 1)
k2_mma() {
    extern __shared__ __align__(16) char sm[];
    u32 smb = smem_u32(sm);

    int tid = threadIdx.x, wid = tid >> 5, lane = tid & 31;
    int src = blockIdx.x / 3, mt = blockIdx.x % 3;
    int b = blockIdx.y, z = blockIdx.z;

    int list[9];
    int n = 0;
    for (int combo = 0; combo < 27; combo++) {
        int e = combo / 3, r = combo % 3;
        int sc = (r == 1) ? e / 3 : e % 3;
        if (sc == src) list[n++] = combo;
    }

    const __half* XH = g_xT_hi + (size_t)(src * 4 + b) * 4096 * 256;

    // A load: 192 rows x 32 chunks = 6144 chunks / 384 thr = 16 iters
#pragma unroll
    for (int i = 0; i < 16; i++) {
        int f = tid + i * 384;
        int row = f >> 5, c = f & 31;
        int cb = list[3 * mt + (row >> 6)];
        size_t so = ((size_t)cb * 64 + (row & 63)) * 256 + c * 8;
        cp16(smb + row * ROWB + c * 16, &g_CM_hi[0][0][0] + so);
    }
    CP_COMMIT();
    load_plane(smb + K2_SMB, XH, z * 512, tid, 384);
    CP_COMMIT();

    int mwarp = wid >> 1, nwarp = wid & 1;   // 6 x 2
    int R0 = mwarp * 32;
    int H = nwarp * 32;

    u32 aoff = (u32)(R0 + (lane & 15)) * ROWB + (lane >> 4) * 16;
    u32 aHi = smb + aoff;
    u32 boff = (u32)(H + (lane & 7) + ((lane >= 16) ? 8 : 0)) * ROWB + ((lane & 8) ? 16 : 0);

    float psum[2][2] = {}, pmax[2][2] = {};

    for (int step = 0; step < 8; step++) {
        if (step < 7) {
            load_plane(smb + K2_SMB + ((step + 1) & 1) * BBUF, XH, z * 512 + (step + 1) * 64,
                       tid, 384);
            CP_COMMIT();
            CP_WAIT1();
        } else {
            CP_WAIT0();
        }
        __syncthreads();

        u32 bHi = smb + K2_SMB + (step & 1) * BBUF + boff;

        float acc[2][4][4] = {};
#pragma unroll
        for (int kk = 0; kk < 16; kk++) {
            u32 kb = kk * 32;
            u32 ah0[4], ah1[4], bh0[4], bh1[4];
            ldsm4(ah0, aHi + kb);
            ldsm4(ah1, aHi + 16 * ROWB + kb);
            ldsm4(bh0, bHi + kb);
            ldsm4(bh1, bHi + 16 * ROWB + kb);
#pragma unroll
            for (int m = 0; m < 2; m++) {
                const u32* ah = m ? ah1 : ah0;
                mma16816(acc[m][0], ah, bh0);
                mma16816(acc[m][1], ah, bh0 + 2);
                mma16816(acc[m][2], ah, bh1);
                mma16816(acc[m][3], ah, bh1 + 2);
            }
        }
#pragma unroll
        for (int m = 0; m < 2; m++)
#pragma unroll
            for (int nt = 0; nt < 4; nt++) {
                float r0 = fmaxf(acc[m][nt][0], 0.f), r1 = fmaxf(acc[m][nt][1], 0.f);
                float r2 = fmaxf(acc[m][nt][2], 0.f), r3 = fmaxf(acc[m][nt][3], 0.f);
                psum[m][0] += r0 + r1;
                psum[m][1] += r2 + r3;
                pmax[m][0] = fmaxf(pmax[m][0], fmaxf(r0, r1));
                pmax[m][1] = fmaxf(pmax[m][1], fmaxf(r2, r3));
            }
        __syncthreads();
    }

#pragma unroll
    for (int m = 0; m < 2; m++)
#pragma unroll
        for (int h = 0; h < 2; h++) {
#pragma unroll
            for (int off = 1; off <= 2; off <<= 1) {
                psum[m][h] += __shfl_xor_sync(0xffffffffu, psum[m][h], off);
                pmax[m][h] = fmaxf(pmax[m][h], __shfl_xor_sync(0xffffffffu, pmax[m][h], off));
            }
        }

    float* ps = (float*)(sm + K2_SMB);       // [192][2]
    float* pm = ps + 384;
    if ((lane & 3) == 0) {
        int g = lane >> 2;
#pragma unroll
        for (int m = 0; m < 2; m++)
#pragma unroll
            for (int h = 0; h < 2; h++) {
                int row = R0 + m * 16 + h * 8 + g;
                ps[row * 2 + nwarp] = psum[m][h];
                pm[row * 2 + nwarp] = pmax[m][h];
            }
    }
    __syncthreads();
    if (tid < 192) {
        float s = ps[tid * 2] + ps[tid * 2 + 1];
        float m = fmaxf(pm[tid * 2], pm[tid * 2 + 1]);
        int cb = list[3 * mt + (tid >> 6)];
        g_pp_sum[cb][b][z][tid & 63] = s;
        g_pp_max[cb][b][z][tid & 63] = m;
    }
}

// ============================================================================
// K3: channel-attention gates per (e, b). grid (9,4), block 256.
// ============================================================================
__global__ void k3_attn(const float* __restrict__ Wrec) {
    int e = blockIdx.x, b = blockIdx.y;
    __shared__ float fS[64], gS[64], hS[64], vout[64];
    __shared__ float redA[4][64], redB[4][64];
    int tid = threadIdx.x;
    int j = tid & 63, p = tid >> 6;

    if (p < 3) {
        float s = 0.f, m = 0.f;
#pragma unroll
        for (int ch = 0; ch < 8; ch++) {
            s += g_pp_sum[e * 3 + p][b][ch][j];
            m = fmaxf(m, g_pp_max[e * 3 + p][b][ch][j]);
        }
        float val = s * (1.f / 4096.f) + m;
        if (p == 0) gS[j] = val;
        else if (p == 1) fS[j] = val;
        else hS[j] = val;
    }
    __syncthreads();

    float gj = gS[j];
    float lmax = -1e30f;
#pragma unroll
    for (int i = p * 16; i < p * 16 + 16; i++) lmax = fmaxf(lmax, fS[i] * gj);
    redA[p][j] = lmax;
    __syncthreads();
    float mx = fmaxf(fmaxf(redA[0][j], redA[1][j]), fmaxf(redA[2][j], redA[3][j]));
    __syncthreads();
    float den = 0.f, num = 0.f;
#pragma unroll
    for (int i = p * 16; i < p * 16 + 16; i++) {
        float ev = expf(fS[i] * gj - mx);
        den += ev;
        num += hS[i] * ev;
    }
    redA[p][j] = den;
    redB[p][j] = num;
    __syncthreads();
    if (p == 0)
        vout[j] = (redB[0][j] + redB[1][j] + redB[2][j] + redB[3][j]) /
                  (redA[0][j] + redA[1][j] + redA[2][j] + redA[3][j]);
    __syncthreads();

    const float* wr = Wrec + ((size_t)e * 256 + tid) * 64;
    float acc = 0.f;
#pragma unroll 8
    for (int q = 0; q < 64; q++) acc = fmaf(vout[q], wr[q], acc);
    g_o[e][b][tid] = 1.f / (1.f + expf(-acc));
}

// ============================================================================
// K4: build gated weights g_W5[b][ct][s][128][256] (fp16 single plane)
//     grid (4, 2, 3), block 256.
// ============================================================================
__global__ void k4_w5(const float* __restrict__ Wqkv) {
    int b = blockIdx.x, ct = blockIdx.y, s = blockIdx.z;
    __shared__ float sAc[128], sBc[128];
    if (threadIdx.x < 128) {
        int c = ct * 128 + threadIdx.x;
        sAc[threadIdx.x] = g_o[s][b][c] + g_o[s + 3][b][c] + g_o[s + 6][b][c];
        sBc[threadIdx.x] = g_o[3 * s][b][c] + g_o[3 * s + 1][b][c] + g_o[3 * s + 2][b][c];
    }
    __syncthreads();
    const float* Wq = Wqkv + (size_t)(3 * s) * 65536 + (size_t)ct * 128 * 256;
    const float* Wk = Wq + 65536;
    const float* Wv = Wk + 65536;
    size_t base = ((size_t)(b * 2 + ct) * 3 + s) * 128 * 256;
    for (int i = threadIdx.x; i < 128 * 256; i += 256) {
        int row = i >> 8, cin = i & 255;
        float w = sAc[row] * (Wq[row * 256 + cin] + Wv[row * 256 + cin])
                + sBc[row] * Wk[row * 256 + cin];
        g_W5[base + i] = __float2half_rn(w);
    }
}

// ============================================================================
// K5: HMMA output GEMM (fp16 1-term), accumulate 3 sources.
//     grid (4 ct of 64 ch, 4 b, 16 hz of 256 hw), block 128 (2m x 2n warps).
//     4 steps of 64 hw per s, double-buffered B. 2 CTAs/SM.
// ============================================================================
__global__ void __launch_bounds__(128, 2)
k5_mma(float* __restrict__ out) {
    extern __shared__ __align__(16) char sm[];
    u32 smb = smem_u32(sm);

    int tid = threadIdx.x, wid = tid >> 5, lane = tid & 31;
    int ct = blockIdx.x, b = blockIdx.y, hz = blockIdx.z;
    int ct2 = ct >> 1, half = ct & 1;

    int mwarp = wid >> 1, nwarp = wid & 1;
    int R0 = mwarp * 32;
    int H = nwarp * 32;

    u32 aoff = (u32)(R0 + (lane & 15)) * ROWB + (lane >> 4) * 16;
    u32 aHi = smb + aoff;
    u32 boff = (u32)(H + (lane & 7) + ((lane >= 16) ? 8 : 0)) * ROWB + ((lane & 8) ? 16 : 0);

    float acc[4][2][4][4] = {};   // [step][m][nt][4]

    // prologue: A(0), B(0, step0)
    {
        const __half* WA = g_W5 + ((size_t)(b * 2 + ct2) * 3) * 128 * 256
                         + (size_t)half * 64 * 256;
#pragma unroll
        for (int i = 0; i < 16; i++) {
            int f = tid + i * 128;
            int row = f >> 5, c = f & 31;
            cp16(smb + row * ROWB + c * 16, WA + (size_t)row * 256 + c * 8);
        }
        CP_COMMIT();
        load_plane(smb + K5_SMB, g_xT_hi + (size_t)b * 4096 * 256, hz * 256, tid, 128);
        CP_COMMIT();
    }

    for (int s = 0; s < 3; s++) {
        const __half* XH = g_xT_hi + (size_t)(s * 4 + b) * 4096 * 256;

#pragma unroll
        for (int step = 0; step < 4; step++) {
            CP_WAIT0();
            __syncthreads();

            if (step < 3) {
                load_plane(smb + K5_SMB + ((step + 1) & 1) * BBUF, XH,
                           hz * 256 + (step + 1) * 64, tid, 128);
                CP_COMMIT();
            }

            u32 bHi = smb + K5_SMB + (step & 1) * BBUF + boff;
#pragma unroll
            for (int kk = 0; kk < 16; kk++) {
                u32 kb = kk * 32;
                u32 ah0[4], ah1[4], bh0[4], bh1[4];
                ldsm4(ah0, aHi + kb);
                ldsm4(ah1, aHi + 16 * ROWB + kb);
                ldsm4(bh0, bHi + kb);
                ldsm4(bh1, bHi + 16 * ROWB + kb);
#pragma unroll
                for (int m = 0; m < 2; m++) {
                    const u32* ah = m ? ah1 : ah0;
                    mma16816(acc[step][m][0], ah, bh0);
                    mma16816(acc[step][m][1], ah, bh0 + 2);
                    mma16816(acc[step][m][2], ah, bh1);
                    mma16816(acc[step][m][3], ah, bh1 + 2);
                }
            }
            __syncthreads();

            if (step == 3 && s < 2) {
                const __half* WA = g_W5 + ((size_t)(b * 2 + ct2) * 3 + (s + 1)) * 128 * 256
                                 + (size_t)half * 64 * 256;
#pragma unroll
                for (int i = 0; i < 16; i++) {
                    int f = tid + i * 128;
                    int row = f >> 5, c = f & 31;
                    cp16(smb + row * ROWB + c * 16, WA + (size_t)row * 256 + c * 8);
                }
                CP_COMMIT();
                load_plane(smb + K5_SMB, g_xT_hi + (size_t)((s + 1) * 4 + b) * 4096 * 256,
                           hz * 256, tid, 128);
                CP_COMMIT();
            }
        }
    }

    // store
    int g = lane >> 2, t = lane & 3;
#pragma unroll
    for (int step = 0; step < 4; step++)
#pragma unroll
        for (int m = 0; m < 2; m++)
#pragma unroll
            for (int nt = 0; nt < 4; nt++) {
                int ch = ct * 64 + R0 + m * 16 + g;
                int col = hz * 256 + step * 64 + H + nt * 8 + 2 * t;
                float2* p0 = (float2*)(out + ((size_t)b * NC + ch) * NHW + col);
                float2* p1 = (float2*)(out + ((size_t)b * NC + ch + 8) * NHW + col);
                *p0 = make_float2(acc[step][m][nt][0], acc[step][m][nt][1]);
                *p1 = make_float2(acc[step][m][nt][2], acc[step][m][nt][3]);
            }
}

// ============================================================================
extern "C" void kernel_launch(void* const* d_in, const int* in_sizes, int n_in,
                              void* d_out, int out_size) {
    (void)in_sizes; (void)n_in; (void)out_size;
    const float* t    = (const float*)d_in[0];
    const float* bb   = (const float*)d_in[1];
    const float* mm   = (const float*)d_in[2];
    const float* Wqkv = (const float*)d_in[3];
    const float* Wred = (const float*)d_in[4];
    const float* Wrec = (const float*)d_in[5];
    float* out = (float*)d_out;

    cudaFuncSetAttribute(k2_mma, cudaFuncAttributeMaxDynamicSharedMemorySize, K2_SMEM);
    cudaFuncSetAttribute(k5_mma, cudaFuncAttributeMaxDynamicSharedMemorySize, K5_SMEM);

    k0_split<<<dim3(12, 8, 16), 256>>>(t, bb, mm);
    k1_cm<<<dim3(27, 4), 256>>>(Wqkv, Wred);
    k2_mma<<<dim3(9, 4, 8), 384, K2_SMEM>>>();
    k3_attn<<<dim3(9, 4), 256>>>(Wrec);
    k4_w5<<<dim3(4, 2, 3), 256>>>(Wqkv);
    k5_mma<<<dim3(4, 4, 16), 128, K5_SMEM>>>(out);
}

// round 12
// speedup vs baseline: 1.3489x; 1.0791x over previous
#include <cuda_runtime.h>
#include <cuda_fp16.h>
#include <cstdint>

typedef unsigned int u32;
typedef unsigned long long u64;

#define NB 4
#define NC 256
#define NHW 4096

// ---------------- device scratch ----------------
__device__ __align__(16) __half g_CM_hi[27][64][256];   // combined matrices (fp16)
__device__ float g_pp_sum[27][4][8][64];
__device__ float g_pp_max[27][4][8][64];
// x transposed, fp16: [src*4+b][hw 4096][cin 256]
__device__ __align__(16) __half g_xT_hi[12u * 4096u * 256u];
// gated output weights (fp16): [b][ct2][s][128][256]
__device__ __align__(16) __half g_W5[4 * 2 * 3 * 128 * 256];

// ---------------- helpers ----------------
static __device__ __forceinline__ u32 smem_u32(const void* p) {
    return (u32)__cvta_generic_to_shared(p);
}
static __device__ __forceinline__ void cp16(u32 d, const void* s) {
    asm volatile("cp.async.cg.shared.global [%0], [%1], 16;" :: "r"(d), "l"(s));
}
#define CP_COMMIT() asm volatile("cp.async.commit_group;" ::: "memory")
#define CP_WAIT1()  asm volatile("cp.async.wait_group 1;" ::: "memory")
#define CP_WAIT0()  asm volatile("cp.async.wait_group 0;" ::: "memory")

static __device__ __forceinline__ void ldsm4(u32* r, u32 a) {
    asm volatile("ldmatrix.sync.aligned.m8n8.x4.shared.b16 {%0,%1,%2,%3}, [%4];"
                 : "=r"(r[0]), "=r"(r[1]), "=r"(r[2]), "=r"(r[3]) : "r"(a));
}
static __device__ __forceinline__ void mma16816(float* d, const u32* a, const u32* b) {
    asm volatile(
        "mma.sync.aligned.m16n8k16.row.col.f32.f16.f16.f32 "
        "{%0,%1,%2,%3},{%4,%5,%6,%7},{%8,%9},{%0,%1,%2,%3};"
        : "+f"(d[0]), "+f"(d[1]), "+f"(d[2]), "+f"(d[3])
        : "r"(a[0]), "r"(a[1]), "r"(a[2]), "r"(a[3]), "r"(b[0]), "r"(b[1]));
}

// smem layout (bytes). Rows: 256 fp16 = 512B + 16B pad = 528B
#define ROWB     528
#define BBUF     33792            // 64 rows * 528 (one plane)
#define K2_SMB   101376           // 192*528
#define K2_SMEM  (K2_SMB + 2 * BBUF)     // 168960
#define K5_SMB   33792
#define K5_SMEM  (K5_SMB + 2 * BBUF)     // 101376

// ============================================================================
// K01: merged k0 (x transpose+fp16) and k1 (combined matrices).
//      grid 1644 x 256 thr. blocks [0,1536): k0; [1536,1644): k1.
// ============================================================================
__global__ void __launch_bounds__(256, 1)
k01(const float* __restrict__ xt, const float* __restrict__ xb,
    const float* __restrict__ xm,
    const float* __restrict__ Wqkv, const float* __restrict__ Wred) {
    __shared__ float sbuf[8320];     // 33280 B: k0 uses [32][257]; k1 uses 2x[64][65]
    int bid = blockIdx.x;

    if (bid < 1536) {
        // ---- k0: transpose + fp16 ----
        float (*s)[257] = (float (*)[257])sbuf;
        int sb = bid >> 7, rem = bid & 127;
        int src = sb >> 2, b = sb & 3;
        const float* xs = (src == 0) ? xt : (src == 1) ? xb : xm;
        int cin0 = (rem >> 4) * 32, hw0 = (rem & 15) * 256;
        const float* base = xs + ((size_t)b * NC + cin0) * NHW + hw0;
        for (int i = threadIdx.x; i < 32 * 256; i += 256) {
            int r = i >> 8, c = i & 255;
            s[r][c] = base[(size_t)r * NHW + c];
        }
        __syncthreads();
        int t = threadIdx.x;
        u32 hb[16];
#pragma unroll
        for (int m = 0; m < 16; m++) {
            __half h0 = __float2half_rn(s[2 * m][t]);
            __half h1 = __float2half_rn(s[2 * m + 1][t]);
            hb[m] = (u32)__half_as_ushort(h0) | ((u32)__half_as_ushort(h1) << 16);
        }
        size_t ro = ((size_t)sb * 4096 + hw0 + t) * 256 + cin0;
        uint4* dh = (uint4*)&g_xT_hi[ro];
#pragma unroll
        for (int q = 0; q < 4; q++)
            dh[q] = make_uint4(hb[4 * q], hb[4 * q + 1], hb[4 * q + 2], hb[4 * q + 3]);
    } else {
        // ---- k1: combined matrices ----
        float (*sA)[65] = (float (*)[65])sbuf;
        float (*sB)[65] = (float (*)[65])(sbuf + 64 * 65);
        int kb = bid - 1536;
        int combo = kb >> 2;
        int cc0 = (kb & 3) * 64;
        int e = combo / 3, r = combo % 3;
        int ii = e / 3, jj = e % 3;
        int w = (r == 0) ? 3 * jj : (r == 1) ? (3 * ii + 1) : (3 * jj + 2);

        int tx = threadIdx.x & 15, ty = threadIdx.x >> 4;
        float acc[4][4] = {};

        const float* A = Wred + (size_t)e * 64 * 256;
        const float* Bm = Wqkv + (size_t)w * 65536;

        for (int k0 = 0; k0 < 256; k0 += 64) {
            for (int idx = threadIdx.x; idx < 4096; idx += 256) {
                int rr = idx >> 6, cl = idx & 63;
                sA[rr][cl] = A[rr * 256 + k0 + cl];
                sB[rr][cl] = Bm[(k0 + rr) * 256 + cc0 + cl];
            }
            __syncthreads();
#pragma unroll
            for (int kk = 0; kk < 64; kk++) {
                float av[4], bv[4];
#pragma unroll
                for (int u = 0; u < 4; u++) av[u] = sA[ty * 4 + u][kk];
#pragma unroll
                for (int v = 0; v < 4; v++) bv[v] = sB[kk][tx * 4 + v];
#pragma unroll
                for (int u = 0; u < 4; u++)
#pragma unroll
                    for (int v = 0; v < 4; v++) acc[u][v] = fmaf(av[u], bv[v], acc[u][v]);
            }
            __syncthreads();
        }
#pragma unroll
        for (int u = 0; u < 4; u++)
#pragma unroll
            for (int v = 0; v < 4; v++)
                g_CM_hi[combo][ty * 4 + u][cc0 + tx * 4 + v] = __float2half_rn(acc[u][v]);
    }
}

// ---- plane loader: 64 hw rows (2048 x 16B chunks) ----
static __device__ __forceinline__ void load_plane(
    u32 dst, const __half* X, int hw0, int tid, int nthr) {
    for (int f = tid; f < 2048; f += nthr) {
        int row = f >> 5, c = f & 31;
        cp16(dst + row * ROWB + c * 16, X + (size_t)(hw0 + row) * 256 + c * 8);
    }
}

// ============================================================================
// K2: HMMA reduced projection (fp16 1-term) + relu + pool.
//     grid (9, 4 b, 8 z of 512 hw), block 384 (6m x 2n warps). 192-row M tiles.
// ============================================================================
__global__ void __launch_bounds__(384, 1)
k2_mma() {
    extern __shared__ __align__(16) char sm[];
    u32 smb = smem_u32(sm);

    int tid = threadIdx.x, wid = tid >> 5, lane = tid & 31;
    int src = blockIdx.x / 3, mt = blockIdx.x % 3;
    int b = blockIdx.y, z = blockIdx.z;

    int list[9];
    int n = 0;
    for (int combo = 0; combo < 27; combo++) {
        int e = combo / 3, r = combo % 3;
        int sc = (r == 1) ? e / 3 : e % 3;
        if (sc == src) list[n++] = combo;
    }

    const __half* XH = g_xT_hi + (size_t)(src * 4 + b) * 4096 * 256;

#pragma unroll
    for (int i = 0; i < 16; i++) {
        int f = tid + i * 384;
        int row = f >> 5, c = f & 31;
        int cb = list[3 * mt + (row >> 6)];
        size_t so = ((size_t)cb * 64 + (row & 63)) * 256 + c * 8;
        cp16(smb + row * ROWB + c * 16, &g_CM_hi[0][0][0] + so);
    }
    CP_COMMIT();
    load_plane(smb + K2_SMB, XH, z * 512, tid, 384);
    CP_COMMIT();

    int mwarp = wid >> 1, nwarp = wid & 1;
    int R0 = mwarp * 32;
    int H = nwarp * 32;

    u32 aoff = (u32)(R0 + (lane & 15)) * ROWB + (lane >> 4) * 16;
    u32 aHi = smb + aoff;
    u32 boff = (u32)(H + (lane & 7) + ((lane >= 16) ? 8 : 0)) * ROWB + ((lane & 8) ? 16 : 0);

    float psum[2][2] = {}, pmax[2][2] = {};

    for (int step = 0; step < 8; step++) {
        if (step < 7) {
            load_plane(smb + K2_SMB + ((step + 1) & 1) * BBUF, XH, z * 512 + (step + 1) * 64,
                       tid, 384);
            CP_COMMIT();
            CP_WAIT1();
        } else {
            CP_WAIT0();
        }
        __syncthreads();

        u32 bHi = smb + K2_SMB + (step & 1) * BBUF + boff;

        float acc[2][4][4] = {};
#pragma unroll
        for (int kk = 0; kk < 16; kk++) {
            u32 kb = kk * 32;
            u32 ah0[4], ah1[4], bh0[4], bh1[4];
            ldsm4(ah0, aHi + kb);
            ldsm4(ah1, aHi + 16 * ROWB + kb);
            ldsm4(bh0, bHi + kb);
            ldsm4(bh1, bHi + 16 * ROWB + kb);
#pragma unroll
            for (int m = 0; m < 2; m++) {
                const u32* ah = m ? ah1 : ah0;
                mma16816(acc[m][0], ah, bh0);
                mma16816(acc[m][1], ah, bh0 + 2);
                mma16816(acc[m][2], ah, bh1);
                mma16816(acc[m][3], ah, bh1 + 2);
            }
        }
#pragma unroll
        for (int m = 0; m < 2; m++)
#pragma unroll
            for (int nt = 0; nt < 4; nt++) {
                float r0 = fmaxf(acc[m][nt][0], 0.f), r1 = fmaxf(acc[m][nt][1], 0.f);
                float r2 = fmaxf(acc[m][nt][2], 0.f), r3 = fmaxf(acc[m][nt][3], 0.f);
                psum[m][0] += r0 + r1;
                psum[m][1] += r2 + r3;
                pmax[m][0] = fmaxf(pmax[m][0], fmaxf(r0, r1));
                pmax[m][1] = fmaxf(pmax[m][1], fmaxf(r2, r3));
            }
        __syncthreads();
    }

#pragma unroll
    for (int m = 0; m < 2; m++)
#pragma unroll
        for (int h = 0; h < 2; h++) {
#pragma unroll
            for (int off = 1; off <= 2; off <<= 1) {
                psum[m][h] += __shfl_xor_sync(0xffffffffu, psum[m][h], off);
                pmax[m][h] = fmaxf(pmax[m][h], __shfl_xor_sync(0xffffffffu, pmax[m][h], off));
            }
        }

    float* ps = (float*)(sm + K2_SMB);       // [192][2]
    float* pm = ps + 384;
    if ((lane & 3) == 0) {
        int g = lane >> 2;
#pragma unroll
        for (int m = 0; m < 2; m++)
#pragma unroll
            for (int h = 0; h < 2; h++) {
                int row = R0 + m * 16 + h * 8 + g;
                ps[row * 2 + nwarp] = psum[m][h];
                pm[row * 2 + nwarp] = pmax[m][h];
            }
    }
    __syncthreads();
    if (tid < 192) {
        float s = ps[tid * 2] + ps[tid * 2 + 1];
        float m = fmaxf(pm[tid * 2], pm[tid * 2 + 1]);
        int cb = list[3 * mt + (tid >> 6)];
        g_pp_sum[cb][b][z][tid & 63] = s;
        g_pp_max[cb][b][z][tid & 63] = m;
    }
}

// ============================================================================
// K34: parallel gates + gated W5 build.
//      grid (4 b, 8 row-tiles of 32, 3 s), block 288 (9 warps, one per e).
// ============================================================================
__global__ void __launch_bounds__(288, 1)
k34(const float* __restrict__ Wrec, const float* __restrict__ Wqkv) {
    __shared__ float fgh[9][3][64];   // [e][pool p][j]  p: 0=g(qr) 1=f(kr) 2=h(vr)
    __shared__ float vout[9][64];
    __shared__ float og[9][32];
    __shared__ float sAc[32], sBc[32];

    int b = blockIdx.x, ct32 = blockIdx.y, s = blockIdx.z;
    int tid = threadIdx.x, wid = tid >> 5, lane = tid & 31;

    // Phase 1: warp `wid` computes pools + softmax + vout for e = wid
    {
        int e = wid;
#pragma unroll
        for (int p = 0; p < 3; p++) {
#pragma unroll
            for (int q = 0; q < 2; q++) {
                int j = lane * 2 + q;
                float sv = 0.f, mv = 0.f;
#pragma unroll
                for (int ch = 0; ch < 8; ch++) {
                    sv += g_pp_sum[e * 3 + p][b][ch][j];
                    mv = fmaxf(mv, g_pp_max[e * 3 + p][b][ch][j]);
                }
                fgh[e][p][j] = sv * (1.f / 4096.f) + mv;
            }
        }
        __syncwarp();
#pragma unroll
        for (int q = 0; q < 2; q++) {
            int j = lane * 2 + q;
            float gj = fgh[e][0][j];
            float mx = -1e30f;
#pragma unroll 8
            for (int i = 0; i < 64; i++) mx = fmaxf(mx, fgh[e][1][i] * gj);
            float den = 0.f, num = 0.f;
#pragma unroll 8
            for (int i = 0; i < 64; i++) {
                float ev = expf(fgh[e][1][i] * gj - mx);
                den += ev;
                num += fgh[e][2][i] * ev;
            }
            vout[e][j] = num / den;
        }
    }
    __syncthreads();

    // Phase 2: gates for this block's 32 channels, all 9 e (288 = 9*32, one pass)
    {
        int e = tid >> 5;
        int c = tid & 31;
        int cg = ct32 * 32 + c;
        const float* wr = Wrec + ((size_t)e * 256 + cg) * 64;
        float acc = 0.f;
#pragma unroll 8
        for (int q = 0; q < 64; q++) acc = fmaf(vout[e][q], wr[q], acc);
        og[e][c] = 1.f / (1.f + expf(-acc));
    }
    __syncthreads();

    if (tid < 32) {
        sAc[tid] = og[s][tid] + og[s + 3][tid] + og[s + 6][tid];
        sBc[tid] = og[3 * s][tid] + og[3 * s + 1][tid] + og[3 * s + 2][tid];
    }
    __syncthreads();

    // Phase 3: W5 build for 32 rows
    int row0 = ct32 * 32;
    const float* Wq = Wqkv + (size_t)(3 * s) * 65536;
    const float* Wk = Wq + 65536;
    const float* Wv = Wk + 65536;
    size_t wbase = ((size_t)(b * 2 + (row0 >> 7)) * 3 + s) * 128 * 256
                 + (size_t)(row0 & 127) * 256;
    for (int i = tid; i < 32 * 256; i += 288) {
        int r = i >> 8, cin = i & 255;
        int c = row0 + r;
        float w = sAc[r] * (Wq[c * 256 + cin] + Wv[c * 256 + cin])
                + sBc[r] * Wk[c * 256 + cin];
        g_W5[wbase + (size_t)r * 256 + cin] = __float2half_rn(w);
    }
}

// ============================================================================
// K5: HMMA output GEMM (fp16 1-term), accumulate 3 sources.
//     grid (4 ct of 64 ch, 4 b, 16 hz of 256 hw), block 128 (2m x 2n warps).
// ============================================================================
__global__ void __launch_bounds__(128, 2)
k5_mma(float* __restrict__ out) {
    extern __shared__ __align__(16) char sm[];
    u32 smb = smem_u32(sm);

    int tid = threadIdx.x, wid = tid >> 5, lane = tid & 31;
    int ct = blockIdx.x, b = blockIdx.y, hz = blockIdx.z;
    int ct2 = ct >> 1, half = ct & 1;

    int mwarp = wid >> 1, nwarp = wid & 1;
    int R0 = mwarp * 32;
    int H = nwarp * 32;

    u32 aoff = (u32)(R0 + (lane & 15)) * ROWB + (lane >> 4) * 16;
    u32 aHi = smb + aoff;
    u32 boff = (u32)(H + (lane & 7) + ((lane >= 16) ? 8 : 0)) * ROWB + ((lane & 8) ? 16 : 0);

    float acc[4][2][4][4] = {};

    {
        const __half* WA = g_W5 + ((size_t)(b * 2 + ct2) * 3) * 128 * 256
                         + (size_t)half * 64 * 256;
#pragma unroll
        for (int i = 0; i < 16; i++) {
            int f = tid + i * 128;
            int row = f >> 5, c = f & 31;
            cp16(smb + row * ROWB + c * 16, WA + (size_t)row * 256 + c * 8);
        }
        CP_COMMIT();
        load_plane(smb + K5_SMB, g_xT_hi + (size_t)b * 4096 * 256, hz * 256, tid, 128);
        CP_COMMIT();
    }

    for (int s = 0; s < 3; s++) {
        const __half* XH = g_xT_hi + (size_t)(s * 4 + b) * 4096 * 256;

#pragma unroll
        for (int step = 0; step < 4; step++) {
            CP_WAIT0();
            __syncthreads();

            if (step < 3) {
                load_plane(smb + K5_SMB + ((step + 1) & 1) * BBUF, XH,
                           hz * 256 + (step + 1) * 64, tid, 128);
                CP_COMMIT();
            }

            u32 bHi = smb + K5_SMB + (step & 1) * BBUF + boff;
#pragma unroll
            for (int kk = 0; kk < 16; kk++) {
                u32 kb = kk * 32;
                u32 ah0[4], ah1[4], bh0[4], bh1[4];
                ldsm4(ah0, aHi + kb);
                ldsm4(ah1, aHi + 16 * ROWB + kb);
                ldsm4(bh0, bHi + kb);
                ldsm4(bh1, bHi + 16 * ROWB + kb);
#pragma unroll
                for (int m = 0; m < 2; m++) {
                    const u32* ah = m ? ah1 : ah0;
                    mma16816(acc[step][m][0], ah, bh0);
                    mma16816(acc[step][m][1], ah, bh0 + 2);
                    mma16816(acc[step][m][2], ah, bh1);
                    mma16816(acc[step][m][3], ah, bh1 + 2);
                }
            }
            __syncthreads();

            if (step == 3 && s < 2) {
                const __half* WA = g_W5 + ((size_t)(b * 2 + ct2) * 3 + (s + 1)) * 128 * 256
                                 + (size_t)half * 64 * 256;
#pragma unroll
                for (int i = 0; i < 16; i++) {
                    int f = tid + i * 128;
                    int row = f >> 5, c = f & 31;
                    cp16(smb + row * ROWB + c * 16, WA + (size_t)row * 256 + c * 8);
                }
                CP_COMMIT();
                load_plane(smb + K5_SMB, g_xT_hi + (size_t)((s + 1) * 4 + b) * 4096 * 256,
                           hz * 256, tid, 128);
                CP_COMMIT();
            }
        }
    }

    int g = lane >> 2, t = lane & 3;
#pragma unroll
    for (int step = 0; step < 4; step++)
#pragma unroll
        for (int m = 0; m < 2; m++)
#pragma unroll
            for (int nt = 0; nt < 4; nt++) {
                int ch = ct * 64 + R0 + m * 16 + g;
                int col = hz * 256 + step * 64 + H + nt * 8 + 2 * t;
                float2* p0 = (float2*)(out + ((size_t)b * NC + ch) * NHW + col);
                float2* p1 = (float2*)(out + ((size_t)b * NC + ch + 8) * NHW + col);
                *p0 = make_float2(acc[step][m][nt][0], acc[step][m][nt][1]);
                *p1 = make_float2(acc[step][m][nt][2], acc[step][m][nt][3]);
            }
}

// ============================================================================
extern "C" void kernel_launch(void* const* d_in, const int* in_sizes, int n_in,
                              void* d_out, int out_size) {
    (void)in_sizes; (void)n_in; (void)out_size;
    const float* t    = (const float*)d_in[0];
    const float* bb   = (const float*)d_in[1];
    const float* mm   = (const float*)d_in[2];
    const float* Wqkv = (const float*)d_in[3];
    const float* Wred = (const float*)d_in[4];
    const float* Wrec = (const float*)d_in[5];
    float* out = (float*)d_out;

    cudaFuncSetAttribute(k2_mma, cudaFuncAttributeMaxDynamicSharedMemorySize, K2_SMEM);
    cudaFuncSetAttribute(k5_mma, cudaFuncAttributeMaxDynamicSharedMemorySize, K5_SMEM);

    k01<<<1644, 256>>>(t, bb, mm, Wqkv, Wred);
    k2_mma<<<dim3(9, 4, 8), 384, K2_SMEM>>>();
    k34<<<dim3(4, 8, 3), 288>>>(Wrec, Wqkv);
    k5_mma<<<dim3(4, 4, 16), 128, K5_SMEM>>>(out);
}

// round 13
// speedup vs baseline: 1.3621x; 1.0098x over previous
#include <cuda_runtime.h>
#include <cuda_fp16.h>
#include <cstdint>

typedef unsigned int u32;
typedef unsigned long long u64;

#define NB 4
#define NC 256
#define NHW 4096

// ---------------- device scratch ----------------
__device__ __align__(16) __half g_CM_hi[27][64][256];   // combined matrices (fp16)
__device__ float g_pp_sum[27][4][8][64];
__device__ float g_pp_max[27][4][8][64];
// x transposed, fp16: [src*4+b][hw 4096][cin 256]
__device__ __align__(16) __half g_xT_hi[12u * 4096u * 256u];
// gated output weights (fp16): [b][ct2][s][128][256]
__device__ __align__(16) __half g_W5[4 * 2 * 3 * 128 * 256];

// ---------------- helpers ----------------
static __device__ __forceinline__ u32 smem_u32(const void* p) {
    return (u32)__cvta_generic_to_shared(p);
}
static __device__ __forceinline__ void cp16(u32 d, const void* s) {
    asm volatile("cp.async.cg.shared.global [%0], [%1], 16;" :: "r"(d), "l"(s));
}
#define CP_COMMIT() asm volatile("cp.async.commit_group;" ::: "memory")
#define CP_WAIT1()  asm volatile("cp.async.wait_group 1;" ::: "memory")
#define CP_WAIT0()  asm volatile("cp.async.wait_group 0;" ::: "memory")

static __device__ __forceinline__ void ldsm4(u32* r, u32 a) {
    asm volatile("ldmatrix.sync.aligned.m8n8.x4.shared.b16 {%0,%1,%2,%3}, [%4];"
                 : "=r"(r[0]), "=r"(r[1]), "=r"(r[2]), "=r"(r[3]) : "r"(a));
}
static __device__ __forceinline__ void mma16816(float* d, const u32* a, const u32* b) {
    asm volatile(
        "mma.sync.aligned.m16n8k16.row.col.f32.f16.f16.f32 "
        "{%0,%1,%2,%3},{%4,%5,%6,%7},{%8,%9},{%0,%1,%2,%3};"
        : "+f"(d[0]), "+f"(d[1]), "+f"(d[2]), "+f"(d[3])
        : "r"(a[0]), "r"(a[1]), "r"(a[2]), "r"(a[3]), "r"(b[0]), "r"(b[1]));
}

// smem layout (bytes). Rows: 256 fp16 = 512B + 16B pad = 528B
#define ROWB     528
#define BBUF     33792            // 64 rows * 528 (one plane)
#define K2_SMB   101376           // 192*528
#define K2_SMEM  (K2_SMB + 2 * BBUF)     // 168960
#define K5_SMB   33792
#define K5_SMEM  (K5_SMB + 2 * BBUF)     // 101376

// ============================================================================
// K01: merged k1 (combined matrices, blocks [0,108)) and k0 (transpose+fp16,
//      blocks [108, 876): 12 sb x 64 hw-tiles of 64). 256 thr.
// ============================================================================
__global__ void __launch_bounds__(256, 1)
k01(const float* __restrict__ xt, const float* __restrict__ xb,
    const float* __restrict__ xm,
    const float* __restrict__ Wqkv, const float* __restrict__ Wred) {
    __shared__ __align__(16) char sbuf[33792];
    int bid = blockIdx.x;
    int tid = threadIdx.x;

    if (bid < 108) {
        // ---- k1: combined matrices ----
        float (*sA)[65] = (float (*)[65])sbuf;
        float (*sB)[65] = (float (*)[65])(sbuf + 64 * 65 * 4);
        int combo = bid >> 2;
        int cc0 = (bid & 3) * 64;
        int e = combo / 3, r = combo % 3;
        int ii = e / 3, jj = e % 3;
        int w = (r == 0) ? 3 * jj : (r == 1) ? (3 * ii + 1) : (3 * jj + 2);

        int tx = tid & 15, ty = tid >> 4;
        float acc[4][4] = {};

        const float* A = Wred + (size_t)e * 64 * 256;
        const float* Bm = Wqkv + (size_t)w * 65536;

        for (int k0 = 0; k0 < 256; k0 += 64) {
            for (int idx = tid; idx < 4096; idx += 256) {
                int rr = idx >> 6, cl = idx & 63;
                sA[rr][cl] = A[rr * 256 + k0 + cl];
                sB[rr][cl] = Bm[(k0 + rr) * 256 + cc0 + cl];
            }
            __syncthreads();
#pragma unroll
            for (int kk = 0; kk < 64; kk++) {
                float av[4], bv[4];
#pragma unroll
                for (int u = 0; u < 4; u++) av[u] = sA[ty * 4 + u][kk];
#pragma unroll
                for (int v = 0; v < 4; v++) bv[v] = sB[kk][tx * 4 + v];
#pragma unroll
                for (int u = 0; u < 4; u++)
#pragma unroll
                    for (int v = 0; v < 4; v++) acc[u][v] = fmaf(av[u], bv[v], acc[u][v]);
            }
            __syncthreads();
        }
#pragma unroll
        for (int u = 0; u < 4; u++)
#pragma unroll
            for (int v = 0; v < 4; v++)
                g_CM_hi[combo][ty * 4 + u][cc0 + tx * 4 + v] = __float2half_rn(acc[u][v]);
    } else {
        // ---- k0: transpose 64 hw x 256 cin, fp16, coalesced writes ----
        __half* sh = (__half*)sbuf;      // [64][264]
        int kb0 = bid - 108;
        int sb = kb0 >> 6, hwt = kb0 & 63;
        int src = sb >> 2, b = sb & 3;
        const float* xs = (src == 0) ? xt : (src == 1) ? xb : xm;
        int hw0 = hwt * 64;
        const float* base = xs + (size_t)b * NC * NHW + hw0;

        int hwl = tid & 63, grp = tid >> 6;
#pragma unroll 4
        for (int i = 0; i < 64; i++) {
            int cin = i * 4 + grp;
            float v = base[(size_t)cin * NHW + hwl];
            sh[hwl * 264 + cin] = __float2half_rn(v);
        }
        __syncthreads();

        // write out: 64 rows x 512B, fully coalesced
        uint4* dst = (uint4*)(g_xT_hi + ((size_t)sb * 4096 + hw0) * 256);
#pragma unroll
        for (int it = 0; it < 8; it++) {
            int idx = it * 256 + tid;
            int row = idx >> 5, ch = idx & 31;
            uint4 v = *(const uint4*)(sbuf + row * 528 + ch * 16);
            dst[row * 32 + ch] = v;
        }
    }
}

// ---- plane loader: 64 hw rows (2048 x 16B chunks) ----
static __device__ __forceinline__ void load_plane(
    u32 dst, const __half* X, int hw0, int tid, int nthr) {
    for (int f = tid; f < 2048; f += nthr) {
        int row = f >> 5, c = f & 31;
        cp16(dst + row * ROWB + c * 16, X + (size_t)(hw0 + row) * 256 + c * 8);
    }
}

// ============================================================================
// K2: HMMA reduced projection (fp16 1-term) + relu + pool.
//     grid (9, 4 b, 8 z of 512 hw), block 192 (3m x 2n warps, M64xN32 tiles).
//     192-row M tiles (3 combos); 8 steps of 64 hw, double-buffered B.
// ============================================================================
__global__ void __launch_bounds__(192, 1)
k2_mma() {
    extern __shared__ __align__(16) char sm[];
    u32 smb = smem_u32(sm);

    int tid = threadIdx.x, wid = tid >> 5, lane = tid & 31;
    int src = blockIdx.x / 3, mt = blockIdx.x % 3;
    int b = blockIdx.y, z = blockIdx.z;

    int list[9];
    int n = 0;
    for (int combo = 0; combo < 27; combo++) {
        int e = combo / 3, r = combo % 3;
        int sc = (r == 1) ? e / 3 : e % 3;
        if (sc == src) list[n++] = combo;
    }

    const __half* XH = g_xT_hi + (size_t)(src * 4 + b) * 4096 * 256;

    // A load: 192 rows x 32 chunks = 6144 chunks / 192 thr = 32 iters
#pragma unroll
    for (int i = 0; i < 32; i++) {
        int f = tid + i * 192;
        int row = f >> 5, c = f & 31;
        int cb = list[3 * mt + (row >> 6)];
        size_t so = ((size_t)cb * 64 + (row & 63)) * 256 + c * 8;
        cp16(smb + row * ROWB + c * 16, &g_CM_hi[0][0][0] + so);
    }
    CP_COMMIT();
    load_plane(smb + K2_SMB, XH, z * 512, tid, 192);
    CP_COMMIT();

    int mwarp = wid >> 1, nwarp = wid & 1;   // 3 x 2
    int R0 = mwarp * 64;
    int H = nwarp * 32;

    u32 aoff = (u32)(R0 + (lane & 15)) * ROWB + (lane >> 4) * 16;
    u32 aHi = smb + aoff;
    u32 boff = (u32)(H + (lane & 7) + ((lane >= 16) ? 8 : 0)) * ROWB + ((lane & 8) ? 16 : 0);

    float psum[4][2] = {}, pmax[4][2] = {};

    for (int step = 0; step < 8; step++) {
        if (step < 7) {
            load_plane(smb + K2_SMB + ((step + 1) & 1) * BBUF, XH, z * 512 + (step + 1) * 64,
                       tid, 192);
            CP_COMMIT();
            CP_WAIT1();
        } else {
            CP_WAIT0();
        }
        __syncthreads();

        u32 bHi = smb + K2_SMB + (step & 1) * BBUF + boff;

        float acc[4][4][4] = {};   // [mf][nf][4]
#pragma unroll
        for (int kk = 0; kk < 16; kk++) {
            u32 kb = kk * 32;
            u32 ah[4][4], bh0[4], bh1[4];
#pragma unroll
            for (int mf = 0; mf < 4; mf++) ldsm4(ah[mf], aHi + mf * 16 * ROWB + kb);
            ldsm4(bh0, bHi + kb);
            ldsm4(bh1, bHi + 16 * ROWB + kb);
#pragma unroll
            for (int mf = 0; mf < 4; mf++) {
                mma16816(acc[mf][0], ah[mf], bh0);
                mma16816(acc[mf][1], ah[mf], bh0 + 2);
                mma16816(acc[mf][2], ah[mf], bh1);
                mma16816(acc[mf][3], ah[mf], bh1 + 2);
            }
        }
#pragma unroll
        for (int mf = 0; mf < 4; mf++)
#pragma unroll
            for (int nf = 0; nf < 4; nf++) {
                float r0 = fmaxf(acc[mf][nf][0], 0.f), r1 = fmaxf(acc[mf][nf][1], 0.f);
                float r2 = fmaxf(acc[mf][nf][2], 0.f), r3 = fmaxf(acc[mf][nf][3], 0.f);
                psum[mf][0] += r0 + r1;
                psum[mf][1] += r2 + r3;
                pmax[mf][0] = fmaxf(pmax[mf][0], fmaxf(r0, r1));
                pmax[mf][1] = fmaxf(pmax[mf][1], fmaxf(r2, r3));
            }
        __syncthreads();
    }

#pragma unroll
    for (int mf = 0; mf < 4; mf++)
#pragma unroll
        for (int h = 0; h < 2; h++) {
#pragma unroll
            for (int off = 1; off <= 2; off <<= 1) {
                psum[mf][h] += __shfl_xor_sync(0xffffffffu, psum[mf][h], off);
                pmax[mf][h] = fmaxf(pmax[mf][h], __shfl_xor_sync(0xffffffffu, pmax[mf][h], off));
            }
        }

    float* ps = (float*)(sm + K2_SMB);       // [192][2]
    float* pm = ps + 384;
    if ((lane & 3) == 0) {
        int g = lane >> 2;
#pragma unroll
        for (int mf = 0; mf < 4; mf++)
#pragma unroll
            for (int h = 0; h < 2; h++) {
                int row = R0 + mf * 16 + h * 8 + g;
                ps[row * 2 + nwarp] = psum[mf][h];
                pm[row * 2 + nwarp] = pmax[mf][h];
            }
    }
    __syncthreads();
    if (tid < 192) {
        float s = ps[tid * 2] + ps[tid * 2 + 1];
        float m = fmaxf(pm[tid * 2], pm[tid * 2 + 1]);
        int cb = list[3 * mt + (tid >> 6)];
        g_pp_sum[cb][b][z][tid & 63] = s;
        g_pp_max[cb][b][z][tid & 63] = m;
    }
}

// ============================================================================
// K34: parallel gates + gated W5 build.
//      grid (4 b, 8 row-tiles of 32, 3 s), block 288 (9 warps, one per e).
// ============================================================================
__global__ void __launch_bounds__(288, 1)
k34(const float* __restrict__ Wrec, const float* __restrict__ Wqkv) {
    __shared__ float fgh[9][3][64];
    __shared__ float vout[9][64];
    __shared__ float og[9][32];
    __shared__ float sAc[32], sBc[32];

    int b = blockIdx.x, ct32 = blockIdx.y, s = blockIdx.z;
    int tid = threadIdx.x, wid = tid >> 5, lane = tid & 31;

    {
        int e = wid;
#pragma unroll
        for (int p = 0; p < 3; p++) {
#pragma unroll
            for (int q = 0; q < 2; q++) {
                int j = lane * 2 + q;
                float sv = 0.f, mv = 0.f;
#pragma unroll
                for (int ch = 0; ch < 8; ch++) {
                    sv += g_pp_sum[e * 3 + p][b][ch][j];
                    mv = fmaxf(mv, g_pp_max[e * 3 + p][b][ch][j]);
                }
                fgh[e][p][j] = sv * (1.f / 4096.f) + mv;
            }
        }
        __syncwarp();
#pragma unroll
        for (int q = 0; q < 2; q++) {
            int j = lane * 2 + q;
            float gj = fgh[e][0][j];
            float mx = -1e30f;
#pragma unroll 8
            for (int i = 0; i < 64; i++) mx = fmaxf(mx, fgh[e][1][i] * gj);
            float den = 0.f, num = 0.f;
#pragma unroll 8
            for (int i = 0; i < 64; i++) {
                float ev = expf(fgh[e][1][i] * gj - mx);
                den += ev;
                num += fgh[e][2][i] * ev;
            }
            vout[e][j] = num / den;
        }
    }
    __syncthreads();

    {
        int e = tid >> 5;
        int c = tid & 31;
        int cg = ct32 * 32 + c;
        const float* wr = Wrec + ((size_t)e * 256 + cg) * 64;
        float acc = 0.f;
#pragma unroll 8
        for (int q = 0; q < 64; q++) acc = fmaf(vout[e][q], wr[q], acc);
        og[e][c] = 1.f / (1.f + expf(-acc));
    }
    __syncthreads();

    if (tid < 32) {
        sAc[tid] = og[s][tid] + og[s + 3][tid] + og[s + 6][tid];
        sBc[tid] = og[3 * s][tid] + og[3 * s + 1][tid] + og[3 * s + 2][tid];
    }
    __syncthreads();

    int row0 = ct32 * 32;
    const float* Wq = Wqkv + (size_t)(3 * s) * 65536;
    const float* Wk = Wq + 65536;
    const float* Wv = Wk + 65536;
    size_t wbase = ((size_t)(b * 2 + (row0 >> 7)) * 3 + s) * 128 * 256
                 + (size_t)(row0 & 127) * 256;
    for (int i = tid; i < 32 * 256; i += 288) {
        int r = i >> 8, cin = i & 255;
        int c = row0 + r;
        float w = sAc[r] * (Wq[c * 256 + cin] + Wv[c * 256 + cin])
                + sBc[r] * Wk[c * 256 + cin];
        g_W5[wbase + (size_t)r * 256 + cin] = __float2half_rn(w);
    }
}

// ============================================================================
// K5: HMMA output GEMM (fp16 1-term), accumulate 3 sources.
//     grid (4 ct of 64 ch, 4 b, 16 hz of 256 hw), block 128 (2m x 2n warps).
// ============================================================================
__global__ void __launch_bounds__(128, 2)
k5_mma(float* __restrict__ out) {
    extern __shared__ __align__(16) char sm[];
    u32 smb = smem_u32(sm);

    int tid = threadIdx.x, wid = tid >> 5, lane = tid & 31;
    int ct = blockIdx.x, b = blockIdx.y, hz = blockIdx.z;
    int ct2 = ct >> 1, half = ct & 1;

    int mwarp = wid >> 1, nwarp = wid & 1;
    int R0 = mwarp * 32;
    int H = nwarp * 32;

    u32 aoff = (u32)(R0 + (lane & 15)) * ROWB + (lane >> 4) * 16;
    u32 aHi = smb + aoff;
    u32 boff = (u32)(H + (lane & 7) + ((lane >= 16) ? 8 : 0)) * ROWB + ((lane & 8) ? 16 : 0);

    float acc[4][2][4][4] = {};

    {
        const __half* WA = g_W5 + ((size_t)(b * 2 + ct2) * 3) * 128 * 256
                         + (size_t)half * 64 * 256;
#pragma unroll
        for (int i = 0; i < 16; i++) {
            int f = tid + i * 128;
            int row = f >> 5, c = f & 31;
            cp16(smb + row * ROWB + c * 16, WA + (size_t)row * 256 + c * 8);
        }
        CP_COMMIT();
        load_plane(smb + K5_SMB, g_xT_hi + (size_t)b * 4096 * 256, hz * 256, tid, 128);
        CP_COMMIT();
    }

    for (int s = 0; s < 3; s++) {
        const __half* XH = g_xT_hi + (size_t)(s * 4 + b) * 4096 * 256;

#pragma unroll
        for (int step = 0; step < 4; step++) {
            CP_WAIT0();
            __syncthreads();

            if (step < 3) {
                load_plane(smb + K5_SMB + ((step + 1) & 1) * BBUF, XH,
                           hz * 256 + (step + 1) * 64, tid, 128);
                CP_COMMIT();
            }

            u32 bHi = smb + K5_SMB + (step & 1) * BBUF + boff;
#pragma unroll
            for (int kk = 0; kk < 16; kk++) {
                u32 kb = kk * 32;
                u32 ah0[4], ah1[4], bh0[4], bh1[4];
                ldsm4(ah0, aHi + kb);
                ldsm4(ah1, aHi + 16 * ROWB + kb);
                ldsm4(bh0, bHi + kb);
                ldsm4(bh1, bHi + 16 * ROWB + kb);
#pragma unroll
                for (int m = 0; m < 2; m++) {
                    const u32* ah = m ? ah1 : ah0;
                    mma16816(acc[step][m][0], ah, bh0);
                    mma16816(acc[step][m][1], ah, bh0 + 2);
                    mma16816(acc[step][m][2], ah, bh1);
                    mma16816(acc[step][m][3], ah, bh1 + 2);
                }
            }
            __syncthreads();

            if (step == 3 && s < 2) {
                const __half* WA = g_W5 + ((size_t)(b * 2 + ct2) * 3 + (s + 1)) * 128 * 256
                                 + (size_t)half * 64 * 256;
#pragma unroll
                for (int i = 0; i < 16; i++) {
                    int f = tid + i * 128;
                    int row = f >> 5, c = f & 31;
                    cp16(smb + row * ROWB + c * 16, WA + (size_t)row * 256 + c * 8);
                }
                CP_COMMIT();
                load_plane(smb + K5_SMB, g_xT_hi + (size_t)((s + 1) * 4 + b) * 4096 * 256,
                           hz * 256, tid, 128);
                CP_COMMIT();
            }
        }
    }

    int g = lane >> 2, t = lane & 3;
#pragma unroll
    for (int step = 0; step < 4; step++)
#pragma unroll
        for (int m = 0; m < 2; m++)
#pragma unroll
            for (int nt = 0; nt < 4; nt++) {
                int ch = ct * 64 + R0 + m * 16 + g;
                int col = hz * 256 + step * 64 + H + nt * 8 + 2 * t;
                float2* p0 = (float2*)(out + ((size_t)b * NC + ch) * NHW + col);
                float2* p1 = (float2*)(out + ((size_t)b * NC + ch + 8) * NHW + col);
                *p0 = make_float2(acc[step][m][nt][0], acc[step][m][nt][1]);
                *p1 = make_float2(acc[step][m][nt][2], acc[step][m][nt][3]);
            }
}

// ============================================================================
extern "C" void kernel_launch(void* const* d_in, const int* in_sizes, int n_in,
                              void* d_out, int out_size) {
    (void)in_sizes; (void)n_in; (void)out_size;
    const float* t    = (const float*)d_in[0];
    const float* bb   = (const float*)d_in[1];
    const float* mm   = (const float*)d_in[2];
    const float* Wqkv = (const float*)d_in[3];
    const float* Wred = (const float*)d_in[4];
    const float* Wrec = (const float*)d_in[5];
    float* out = (float*)d_out;

    cudaFuncSetAttribute(k2_mma, cudaFuncAttributeMaxDynamicSharedMemorySize, K2_SMEM);
    cudaFuncSetAttribute(k5_mma, cudaFuncAttributeMaxDynamicSharedMemorySize, K5_SMEM);

    k01<<<876, 256>>>(t, bb, mm, Wqkv, Wred);
    k2_mma<<<dim3(9, 4, 8), 192, K2_SMEM>>>();
    k34<<<dim3(4, 8, 3), 288>>>(Wrec, Wqkv);
    k5_mma<<<dim3(4, 4, 16), 128, K5_SMEM>>>(out);
}

// round 14
// speedup vs baseline: 1.3650x; 1.0022x over previous
#include <cuda_runtime.h>
#include <cuda_fp16.h>
#include <cstdint>

typedef unsigned int u32;
typedef unsigned long long u64;

#define NB 4
#define NC 256
#define NHW 4096

// ---------------- device scratch ----------------
__device__ __align__(16) __half g_CM_hi[27][64][256];   // combined matrices (fp16)
__device__ float g_pp_sum[27][4][8][64];
__device__ float g_pp_max[27][4][8][64];
// x transposed, fp16: [src*4+b][hw 4096][cin 256]
__device__ __align__(16) __half g_xT_hi[12u * 4096u * 256u];
// gated output weights (fp16): [b][ct2][s][128][256]
__device__ __align__(16) __half g_W5[4 * 2 * 3 * 128 * 256];

// ---------------- helpers ----------------
static __device__ __forceinline__ u32 smem_u32(const void* p) {
    return (u32)__cvta_generic_to_shared(p);
}
static __device__ __forceinline__ void cp16(u32 d, const void* s) {
    asm volatile("cp.async.cg.shared.global [%0], [%1], 16;" :: "r"(d), "l"(s));
}
#define CP_COMMIT() asm volatile("cp.async.commit_group;" ::: "memory")
#define CP_WAIT1()  asm volatile("cp.async.wait_group 1;" ::: "memory")
#define CP_WAIT0()  asm volatile("cp.async.wait_group 0;" ::: "memory")

static __device__ __forceinline__ void ldsm4(u32* r, u32 a) {
    asm volatile("ldmatrix.sync.aligned.m8n8.x4.shared.b16 {%0,%1,%2,%3}, [%4];"
                 : "=r"(r[0]), "=r"(r[1]), "=r"(r[2]), "=r"(r[3]) : "r"(a));
}
static __device__ __forceinline__ void mma16816(float* d, const u32* a, const u32* b) {
    asm volatile(
        "mma.sync.aligned.m16n8k16.row.col.f32.f16.f16.f32 "
        "{%0,%1,%2,%3},{%4,%5,%6,%7},{%8,%9},{%0,%1,%2,%3};"
        : "+f"(d[0]), "+f"(d[1]), "+f"(d[2]), "+f"(d[3])
        : "r"(a[0]), "r"(a[1]), "r"(a[2]), "r"(a[3]), "r"(b[0]), "r"(b[1]));
}

// smem layout (bytes). Rows: 256 fp16 = 512B + 16B pad = 528B
#define ROWB     528
#define BBUF     33792            // 64 rows * 528 (one plane)
#define KG_SMB   33792            // A [64 rows]
#define KG_SMEM  (KG_SMB + 2 * BBUF)     // 101376 — used by k2 and k5

// ============================================================================
// K01: merged k1 (combined matrices, blocks [0,108)) and k0 (transpose+fp16,
//      blocks [108, 876): 12 sb x 64 hw-tiles of 64). 256 thr.
// ============================================================================
__global__ void __launch_bounds__(256, 1)
k01(const float* __restrict__ xt, const float* __restrict__ xb,
    const float* __restrict__ xm,
    const float* __restrict__ Wqkv, const float* __restrict__ Wred) {
    __shared__ __align__(16) char sbuf[33792];
    int bid = blockIdx.x;
    int tid = threadIdx.x;

    if (bid < 108) {
        // ---- k1: combined matrices ----
        float (*sA)[65] = (float (*)[65])sbuf;
        float (*sB)[65] = (float (*)[65])(sbuf + 64 * 65 * 4);
        int combo = bid >> 2;
        int cc0 = (bid & 3) * 64;
        int e = combo / 3, r = combo % 3;
        int ii = e / 3, jj = e % 3;
        int w = (r == 0) ? 3 * jj : (r == 1) ? (3 * ii + 1) : (3 * jj + 2);

        int tx = tid & 15, ty = tid >> 4;
        float acc[4][4] = {};

        const float* A = Wred + (size_t)e * 64 * 256;
        const float* Bm = Wqkv + (size_t)w * 65536;

        for (int k0 = 0; k0 < 256; k0 += 64) {
            for (int idx = tid; idx < 4096; idx += 256) {
                int rr = idx >> 6, cl = idx & 63;
                sA[rr][cl] = A[rr * 256 + k0 + cl];
                sB[rr][cl] = Bm[(k0 + rr) * 256 + cc0 + cl];
            }
            __syncthreads();
#pragma unroll
            for (int kk = 0; kk < 64; kk++) {
                float av[4], bv[4];
#pragma unroll
                for (int u = 0; u < 4; u++) av[u] = sA[ty * 4 + u][kk];
#pragma unroll
                for (int v = 0; v < 4; v++) bv[v] = sB[kk][tx * 4 + v];
#pragma unroll
                for (int u = 0; u < 4; u++)
#pragma unroll
                    for (int v = 0; v < 4; v++) acc[u][v] = fmaf(av[u], bv[v], acc[u][v]);
            }
            __syncthreads();
        }
#pragma unroll
        for (int u = 0; u < 4; u++)
#pragma unroll
            for (int v = 0; v < 4; v++)
                g_CM_hi[combo][ty * 4 + u][cc0 + tx * 4 + v] = __float2half_rn(acc[u][v]);
    } else {
        // ---- k0: transpose 64 hw x 256 cin, fp16, coalesced writes ----
        __half* sh = (__half*)sbuf;      // [64][264]
        int kb0 = bid - 108;
        int sb = kb0 >> 6, hwt = kb0 & 63;
        int src = sb >> 2, b = sb & 3;
        const float* xs = (src == 0) ? xt : (src == 1) ? xb : xm;
        int hw0 = hwt * 64;
        const float* base = xs + (size_t)b * NC * NHW + hw0;

        int hwl = tid & 63, grp = tid >> 6;
#pragma unroll 4
        for (int i = 0; i < 64; i++) {
            int cin = i * 4 + grp;
            float v = base[(size_t)cin * NHW + hwl];
            sh[hwl * 264 + cin] = __float2half_rn(v);
        }
        __syncthreads();

        uint4* dst = (uint4*)(g_xT_hi + ((size_t)sb * 4096 + hw0) * 256);
#pragma unroll
        for (int it = 0; it < 8; it++) {
            int idx = it * 256 + tid;
            int row = idx >> 5, ch = idx & 31;
            uint4 v = *(const uint4*)(sbuf + row * 528 + ch * 16);
            dst[row * 32 + ch] = v;
        }
    }
}

// ---- plane loader: 64 hw rows (2048 x 16B chunks) ----
static __device__ __forceinline__ void load_plane(
    u32 dst, const __half* X, int hw0, int tid, int nthr) {
    for (int f = tid; f < 2048; f += nthr) {
        int row = f >> 5, c = f & 31;
        cp16(dst + row * ROWB + c * 16, X + (size_t)(hw0 + row) * 256 + c * 8);
    }
}

// ============================================================================
// K2: HMMA reduced projection (fp16 1-term) + relu + pool.
//     grid (27 combos, 4 b, 8 z of 512 hw), block 128 (2m x 2n warps).
//     M tile = 64 rows (one combo); 8 steps of 64 hw, double-buffered B.
//     2 CTAs/SM (smem 99KB, regs ~130).
// ============================================================================
__global__ void __launch_bounds__(128, 2)
k2_mma() {
    extern __shared__ __align__(16) char sm[];
    u32 smb = smem_u32(sm);

    int tid = threadIdx.x, wid = tid >> 5, lane = tid & 31;
    int combo = blockIdx.x;
    int b = blockIdx.y, z = blockIdx.z;

    int e = combo / 3, r = combo % 3;
    int src = (r == 1) ? e / 3 : e % 3;

    const __half* XH = g_xT_hi + (size_t)(src * 4 + b) * 4096 * 256;

    // A load: 64 rows x 32 chunks = 2048 chunks / 128 thr = 16 iters
#pragma unroll
    for (int i = 0; i < 16; i++) {
        int f = tid + i * 128;
        int row = f >> 5, c = f & 31;
        cp16(smb + row * ROWB + c * 16,
             &g_CM_hi[combo][0][0] + (size_t)row * 256 + c * 8);
    }
    CP_COMMIT();
    load_plane(smb + KG_SMB, XH, z * 512, tid, 128);
    CP_COMMIT();

    int mwarp = wid >> 1, nwarp = wid & 1;   // 2 x 2
    int R0 = mwarp * 32;
    int H = nwarp * 32;

    u32 aoff = (u32)(R0 + (lane & 15)) * ROWB + (lane >> 4) * 16;
    u32 aHi = smb + aoff;
    u32 boff = (u32)(H + (lane & 7) + ((lane >= 16) ? 8 : 0)) * ROWB + ((lane & 8) ? 16 : 0);

    float psum[2][2] = {}, pmax[2][2] = {};   // [m-frag][row-half]

    for (int step = 0; step < 8; step++) {
        if (step < 7) {
            load_plane(smb + KG_SMB + ((step + 1) & 1) * BBUF, XH, z * 512 + (step + 1) * 64,
                       tid, 128);
            CP_COMMIT();
            CP_WAIT1();
        } else {
            CP_WAIT0();
        }
        __syncthreads();

        u32 bHi = smb + KG_SMB + (step & 1) * BBUF + boff;

        float acc[2][4][4] = {};   // [m][nt][4]
#pragma unroll
        for (int kk = 0; kk < 16; kk++) {
            u32 kb = kk * 32;
            u32 ah0[4], ah1[4], bh0[4], bh1[4];
            ldsm4(ah0, aHi + kb);
            ldsm4(ah1, aHi + 16 * ROWB + kb);
            ldsm4(bh0, bHi + kb);
            ldsm4(bh1, bHi + 16 * ROWB + kb);
#pragma unroll
            for (int m = 0; m < 2; m++) {
                const u32* ah = m ? ah1 : ah0;
                mma16816(acc[m][0], ah, bh0);
                mma16816(acc[m][1], ah, bh0 + 2);
                mma16816(acc[m][2], ah, bh1);
                mma16816(acc[m][3], ah, bh1 + 2);
            }
        }
#pragma unroll
        for (int m = 0; m < 2; m++)
#pragma unroll
            for (int nt = 0; nt < 4; nt++) {
                float r0 = fmaxf(acc[m][nt][0], 0.f), r1 = fmaxf(acc[m][nt][1], 0.f);
                float r2 = fmaxf(acc[m][nt][2], 0.f), r3 = fmaxf(acc[m][nt][3], 0.f);
                psum[m][0] += r0 + r1;
                psum[m][1] += r2 + r3;
                pmax[m][0] = fmaxf(pmax[m][0], fmaxf(r0, r1));
                pmax[m][1] = fmaxf(pmax[m][1], fmaxf(r2, r3));
            }
        __syncthreads();
    }

    // reduce across the 4 quad-lanes (hw columns)
#pragma unroll
    for (int m = 0; m < 2; m++)
#pragma unroll
        for (int h = 0; h < 2; h++) {
#pragma unroll
            for (int off = 1; off <= 2; off <<= 1) {
                psum[m][h] += __shfl_xor_sync(0xffffffffu, psum[m][h], off);
                pmax[m][h] = fmaxf(pmax[m][h], __shfl_xor_sync(0xffffffffu, pmax[m][h], off));
            }
        }

    float* ps = (float*)(sm + KG_SMB);       // [64][2]
    float* pm = ps + 128;
    if ((lane & 3) == 0) {
        int g = lane >> 2;
#pragma unroll
        for (int m = 0; m < 2; m++)
#pragma unroll
            for (int h = 0; h < 2; h++) {
                int row = R0 + m * 16 + h * 8 + g;
                ps[row * 2 + nwarp] = psum[m][h];
                pm[row * 2 + nwarp] = pmax[m][h];
            }
    }
    __syncthreads();
    if (tid < 64) {
        float s = ps[tid * 2] + ps[tid * 2 + 1];
        float m = fmaxf(pm[tid * 2], pm[tid * 2 + 1]);
        g_pp_sum[combo][b][z][tid] = s;
        g_pp_max[combo][b][z][tid] = m;
    }
}

// ============================================================================
// K34: parallel gates + gated W5 build.
//      grid (4 b, 8 row-tiles of 32, 3 s), block 288 (9 warps, one per e).
// ============================================================================
__global__ void __launch_bounds__(288, 1)
k34(const float* __restrict__ Wrec, const float* __restrict__ Wqkv) {
    __shared__ float fgh[9][3][64];
    __shared__ float vout[9][64];
    __shared__ float og[9][32];
    __shared__ float sAc[32], sBc[32];

    int b = blockIdx.x, ct32 = blockIdx.y, s = blockIdx.z;
    int tid = threadIdx.x, wid = tid >> 5, lane = tid & 31;

    {
        int e = wid;
#pragma unroll
        for (int p = 0; p < 3; p++) {
#pragma unroll
            for (int q = 0; q < 2; q++) {
                int j = lane * 2 + q;
                float sv = 0.f, mv = 0.f;
#pragma unroll
                for (int ch = 0; ch < 8; ch++) {
                    sv += g_pp_sum[e * 3 + p][b][ch][j];
                    mv = fmaxf(mv, g_pp_max[e * 3 + p][b][ch][j]);
                }
                fgh[e][p][j] = sv * (1.f / 4096.f) + mv;
            }
        }
        __syncwarp();
#pragma unroll
        for (int q = 0; q < 2; q++) {
            int j = lane * 2 + q;
            float gj = fgh[e][0][j];
            float mx = -1e30f;
#pragma unroll 8
            for (int i = 0; i < 64; i++) mx = fmaxf(mx, fgh[e][1][i] * gj);
            float den = 0.f, num = 0.f;
#pragma unroll 8
            for (int i = 0; i < 64; i++) {
                float ev = expf(fgh[e][1][i] * gj - mx);
                den += ev;
                num += fgh[e][2][i] * ev;
            }
            vout[e][j] = num / den;
        }
    }
    __syncthreads();

    {
        int e = tid >> 5;
        int c = tid & 31;
        int cg = ct32 * 32 + c;
        const float* wr = Wrec + ((size_t)e * 256 + cg) * 64;
        float acc = 0.f;
#pragma unroll 8
        for (int q = 0; q < 64; q++) acc = fmaf(vout[e][q], wr[q], acc);
        og[e][c] = 1.f / (1.f + expf(-acc));
    }
    __syncthreads();

    if (tid < 32) {
        sAc[tid] = og[s][tid] + og[s + 3][tid] + og[s + 6][tid];
        sBc[tid] = og[3 * s][tid] + og[3 * s + 1][tid] + og[3 * s + 2][tid];
    }
    __syncthreads();

    int row0 = ct32 * 32;
    const float* Wq = Wqkv + (size_t)(3 * s) * 65536;
    const float* Wk = Wq + 65536;
    const float* Wv = Wk + 65536;
    size_t wbase = ((size_t)(b * 2 + (row0 >> 7)) * 3 + s) * 128 * 256
                 + (size_t)(row0 & 127) * 256;
    for (int i = tid; i < 32 * 256; i += 288) {
        int r = i >> 8, cin = i & 255;
        int c = row0 + r;
        float w = sAc[r] * (Wq[c * 256 + cin] + Wv[c * 256 + cin])
                + sBc[r] * Wk[c * 256 + cin];
        g_W5[wbase + (size_t)r * 256 + cin] = __float2half_rn(w);
    }
}

// ============================================================================
// K5: HMMA output GEMM (fp16 1-term), accumulate 3 sources.
//     grid (4 ct of 64 ch, 4 b, 16 hz of 256 hw), block 128 (2m x 2n warps).
// ============================================================================
__global__ void __launch_bounds__(128, 2)
k5_mma(float* __restrict__ out) {
    extern __shared__ __align__(16) char sm[];
    u32 smb = smem_u32(sm);

    int tid = threadIdx.x, wid = tid >> 5, lane = tid & 31;
    int ct = blockIdx.x, b = blockIdx.y, hz = blockIdx.z;
    int ct2 = ct >> 1, half = ct & 1;

    int mwarp = wid >> 1, nwarp = wid & 1;
    int R0 = mwarp * 32;
    int H = nwarp * 32;

    u32 aoff = (u32)(R0 + (lane & 15)) * ROWB + (lane >> 4) * 16;
    u32 aHi = smb + aoff;
    u32 boff = (u32)(H + (lane & 7) + ((lane >= 16) ? 8 : 0)) * ROWB + ((lane & 8) ? 16 : 0);

    float acc[4][2][4][4] = {};

    {
        const __half* WA = g_W5 + ((size_t)(b * 2 + ct2) * 3) * 128 * 256
                         + (size_t)half * 64 * 256;
#pragma unroll
        for (int i = 0; i < 16; i++) {
            int f = tid + i * 128;
            int row = f >> 5, c = f & 31;
            cp16(smb + row * ROWB + c * 16, WA + (size_t)row * 256 + c * 8);
        }
        CP_COMMIT();
        load_plane(smb + KG_SMB, g_xT_hi + (size_t)b * 4096 * 256, hz * 256, tid, 128);
        CP_COMMIT();
    }

    for (int s = 0; s < 3; s++) {
        const __half* XH = g_xT_hi + (size_t)(s * 4 + b) * 4096 * 256;

#pragma unroll
        for (int step = 0; step < 4; step++) {
            CP_WAIT0();
            __syncthreads();

            if (step < 3) {
                load_plane(smb + KG_SMB + ((step + 1) & 1) * BBUF, XH,
                           hz * 256 + (step + 1) * 64, tid, 128);
                CP_COMMIT();
            }

            u32 bHi = smb + KG_SMB + (step & 1) * BBUF + boff;
#pragma unroll
            for (int kk = 0; kk < 16; kk++) {
                u32 kb = kk * 32;
                u32 ah0[4], ah1[4], bh0[4], bh1[4];
                ldsm4(ah0, aHi + kb);
                ldsm4(ah1, aHi + 16 * ROWB + kb);
                ldsm4(bh0, bHi + kb);
                ldsm4(bh1, bHi + 16 * ROWB + kb);
#pragma unroll
                for (int m = 0; m < 2; m++) {
                    const u32* ah = m ? ah1 : ah0;
                    mma16816(acc[step][m][0], ah, bh0);
                    mma16816(acc[step][m][1], ah, bh0 + 2);
                    mma16816(acc[step][m][2], ah, bh1);
                    mma16816(acc[step][m][3], ah, bh1 + 2);
                }
            }
            __syncthreads();

            if (step == 3 && s < 2) {
                const __half* WA = g_W5 + ((size_t)(b * 2 + ct2) * 3 + (s + 1)) * 128 * 256
                                 + (size_t)half * 64 * 256;
#pragma unroll
                for (int i = 0; i < 16; i++) {
                    int f = tid + i * 128;
                    int row = f >> 5, c = f & 31;
                    cp16(smb + row * ROWB + c * 16, WA + (size_t)row * 256 + c * 8);
                }
                CP_COMMIT();
                load_plane(smb + KG_SMB, g_xT_hi + (size_t)((s + 1) * 4 + b) * 4096 * 256,
                           hz * 256, tid, 128);
                CP_COMMIT();
            }
        }
    }

    int g = lane >> 2, t = lane & 3;
#pragma unroll
    for (int step = 0; step < 4; step++)
#pragma unroll
        for (int m = 0; m < 2; m++)
#pragma unroll
            for (int nt = 0; nt < 4; nt++) {
                int ch = ct * 64 + R0 + m * 16 + g;
                int col = hz * 256 + step * 64 + H + nt * 8 + 2 * t;
                float2* p0 = (float2*)(out + ((size_t)b * NC + ch) * NHW + col);
                float2* p1 = (float2*)(out + ((size_t)b * NC + ch + 8) * NHW + col);
                *p0 = make_float2(acc[step][m][nt][0], acc[step][m][nt][1]);
                *p1 = make_float2(acc[step][m][nt][2], acc[step][m][nt][3]);
            }
}

// ============================================================================
extern "C" void kernel_launch(void* const* d_in, const int* in_sizes, int n_in,
                              void* d_out, int out_size) {
    (void)in_sizes; (void)n_in; (void)out_size;
    const float* t    = (const float*)d_in[0];
    const float* bb   = (const float*)d_in[1];
    const float* mm   = (const float*)d_in[2];
    const float* Wqkv = (const float*)d_in[3];
    const float* Wred = (const float*)d_in[4];
    const float* Wrec = (const float*)d_in[5];
    float* out = (float*)d_out;

    cudaFuncSetAttribute(k2_mma, cudaFuncAttributeMaxDynamicSharedMemorySize, KG_SMEM);
    cudaFuncSetAttribute(k5_mma, cudaFuncAttributeMaxDynamicSharedMemorySize, KG_SMEM);

    k01<<<876, 256>>>(t, bb, mm, Wqkv, Wred);
    k2_mma<<<dim3(27, 4, 8), 128, KG_SMEM>>>();
    k34<<<dim3(4, 8, 3), 288>>>(Wrec, Wqkv);
    k5_mma<<<dim3(4, 4, 16), 128, KG_SMEM>>>(out);
}